// round 9
// baseline (speedup 1.0000x reference)
#include <cuda_runtime.h>
#include <cuda_fp16.h>
#include <cstdint>
#include <math.h>

#define B_  8
#define C_  256
#define Hh  80
#define Ww  80
#define HW  6400
#define NPIX 51200
#define EPSF 1e-5f

#define KC 32
#define STAGES 4
#define TSTRH 40                 // smem row stride in halfs (80B): LDSM conflict-free
#define ST_B (128*TSTRH*2)       // 10240 B per operand stage
#define SMEM_BYTES (STAGES*2*ST_B)   // 81920 B per CTA

// ---------------- scratch ----------------
__device__ __half g_xT [(size_t)NPIX*256];
__device__ __half g_qkv[(size_t)NPIX*768];
__device__ __half g_y2 [(size_t)NPIX*256];
__device__ __half g_x1h[(size_t)NPIX*256];
__device__ float  g_x1f[(size_t)NPIX*256];
__device__ __half g_h  [(size_t)NPIX*512];
__device__ __half g_w  [524288];

// ---------------- helpers ----------------
__device__ __forceinline__ uint32_t s2u(const void* p){
    uint32_t a; asm("{ .reg .u64 t; cvta.to.shared.u64 t, %1; cvt.u32.u64 %0, t; }" : "=r"(a) : "l"(p)); return a;
}
#define CPA16(d,s) asm volatile("cp.async.cg.shared.global [%0], [%1], 16;" :: "r"(d), "l"(s))
#define CPCOMMIT() asm volatile("cp.async.commit_group;" ::: "memory")
#define CPWAIT(n)  asm volatile("cp.async.wait_group %0;" :: "n"(n) : "memory")
#define LDSM4(r0,r1,r2,r3,a) \
    asm volatile("ldmatrix.sync.aligned.m8n8.x4.shared.b16 {%0,%1,%2,%3}, [%4];" \
        : "=r"(r0), "=r"(r1), "=r"(r2), "=r"(r3) : "r"(a))

__device__ __forceinline__ void mma16(float* d, const uint32_t* a, uint32_t b0, uint32_t b1){
    asm volatile("mma.sync.aligned.m16n8k16.row.col.f32.f16.f16.f32 "
        "{%0,%1,%2,%3}, {%4,%5,%6,%7}, {%8,%9}, {%0,%1,%2,%3};"
        : "+f"(d[0]), "+f"(d[1]), "+f"(d[2]), "+f"(d[3])
        : "r"(a[0]), "r"(a[1]), "r"(a[2]), "r"(a[3]), "r"(b0), "r"(b1));
}

// ---------------- fp16 mma.sync GEMM, 128x128 tile, 4 warps (64x64 warp tile) ----------------
// MODE 0: Ch = acc + bias[n]                      -> qkv half (Cstride 768)
// MODE 1: Ch = half(acc+bias+resx), Cf = full     -> x1h / x1f  (resx = x[b][c][hw] fp32)
// MODE 2: Ch = half(silu(acc*sc+sh))              -> h half (Cstride 512)
// MODE 3: Cf = acc*sc+sh + res -> out[b][n][pixl] (smem-staged transposed store; res fp32)
template<int MODE>
__global__ __launch_bounds__(128, 2) void gemm_mma(
    const __half* __restrict__ A, const __half* __restrict__ Bw,
    __half* __restrict__ Ch, float* __restrict__ Cf, int Ktot, int Cstride,
    const float* __restrict__ bias, const float* __restrict__ res,
    const float* __restrict__ gg, const float* __restrict__ bb,
    const float* __restrict__ mm, const float* __restrict__ vv)
{
    extern __shared__ float smemf[];
    const uint32_t smem_b = s2u(smemf);

    const int tid  = threadIdx.x;
    const int wid  = tid >> 5;
    const int lane = tid & 31;
    const int wm   = wid & 1;         // 2 warps in M (64 rows)
    const int wn   = wid >> 1;        // 2 warps in N (64 cols)
    const int lr   = lane >> 2;
    const int lc   = lane & 3;
    const int m0   = blockIdx.y * 128;
    const int n0   = blockIdx.x * 128;

    // LDSM per-thread byte offsets within a stage
    const uint32_t aoff = (uint32_t)(((wm*64 + ((lane>>3)&1)*8 + (lane&7))*TSTRH + (lane>>4)*8) * 2);
    const uint32_t boff = (uint32_t)(((wn*64 + (lane>>4)*8 + (lane&7))*TSTRH + ((lane>>3)&1)*8) * 2);

    float d[4][8][4];
#pragma unroll
    for (int i = 0; i < 4; i++)
#pragma unroll
        for (int j = 0; j < 8; j++)
#pragma unroll
            for (int e = 0; e < 4; e++) d[i][j][e] = 0.f;

    const int nch = Ktot / KC;

    auto load = [&](int cc){
        const int s = cc % STAGES;
        const __half* Ab = A + (size_t)m0 * Ktot + cc*KC;
        const uint32_t da = smem_b + (2*s)*ST_B;
#pragma unroll
        for (int t = 0; t < 4; t++){
            int i = tid + t*128;
            int r = i >> 2, c = i & 3;
            CPA16(da + r*TSTRH*2 + c*16, (const void*)(Ab + (size_t)r*Ktot + c*8));
        }
        const __half* Bb = Bw + (size_t)n0 * Ktot + cc*KC;
        const uint32_t db = smem_b + (2*s+1)*ST_B;
#pragma unroll
        for (int t = 0; t < 4; t++){
            int i = tid + t*128;
            int r = i >> 2, c = i & 3;
            CPA16(db + r*TSTRH*2 + c*16, (const void*)(Bb + (size_t)r*Ktot + c*8));
        }
        CPCOMMIT();
    };

    load(0); load(1); load(2);

    for (int cc = 0; cc < nch; cc++){
        const int rem = nch - 1 - cc;
        if (rem >= 2)      CPWAIT(2);
        else if (rem == 1) CPWAIT(1);
        else               CPWAIT(0);
        __syncthreads();
        if (cc + 3 < nch) load(cc + 3);

        const int s = cc % STAGES;
        const uint32_t aBase = smem_b + (2*s)*ST_B + aoff;
        const uint32_t bBase = smem_b + (2*s+1)*ST_B + boff;
#pragma unroll
        for (int kk = 0; kk < 2; kk++){
            uint32_t a[4][4], bf[4][4];
#pragma unroll
            for (int mi = 0; mi < 4; mi++)
                LDSM4(a[mi][0], a[mi][1], a[mi][2], a[mi][3],
                      aBase + mi*(16*TSTRH*2) + kk*32);
#pragma unroll
            for (int np = 0; np < 4; np++)
                LDSM4(bf[np][0], bf[np][1], bf[np][2], bf[np][3],
                      bBase + np*(16*TSTRH*2) + kk*32);
#pragma unroll
            for (int np = 0; np < 4; np++)
#pragma unroll
                for (int mi = 0; mi < 4; mi++){
                    mma16(d[mi][2*np],   a[mi], bf[np][0], bf[np][1]);
                    mma16(d[mi][2*np+1], a[mi], bf[np][2], bf[np][3]);
                }
        }
    }

    // ---------------- epilogue ----------------
    const int lc2 = lc * 2;

    if (MODE != 3){
        const int bidx  = (MODE == 1) ? m0 / HW : 0;
        const int pixl0 = (MODE == 1) ? m0 - bidx*HW : 0;
        const float* xb = (MODE == 1) ? res + (size_t)bidx*C_*HW : (const float*)0;
#pragma unroll
        for (int mi = 0; mi < 4; mi++){
#pragma unroll
            for (int rr = 0; rr < 2; rr++){
                const int rl = wm*64 + mi*16 + lr + rr*8;
                const int r  = m0 + rl;
                __half* crow = Ch + (size_t)r*Cstride + n0 + wn*64;
                float* crow2 = (MODE == 1) ? Cf + (size_t)r*256 + n0 + wn*64 : (float*)0;
                const int pixl = pixl0 + rl;
#pragma unroll
                for (int ni = 0; ni < 8; ni++){
                    const int c = ni*8 + lc2;
                    const int gc = n0 + wn*64 + c;
                    float v0 = d[mi][ni][rr*2+0];
                    float v1 = d[mi][ni][rr*2+1];
                    if (MODE == 0){
                        v0 += bias[gc]; v1 += bias[gc+1];
                        *(__half2*)(crow + c) = __floats2half2_rn(v0, v1);
                    } else if (MODE == 1){
                        v0 += bias[gc]   + xb[(size_t)gc*HW + pixl];
                        v1 += bias[gc+1] + xb[(size_t)(gc+1)*HW + pixl];
                        *(float2*)(crow2 + c) = make_float2(v0, v1);
                        *(__half2*)(crow + c) = __floats2half2_rn(v0, v1);
                    } else { // MODE 2
                        float i0 = gg[gc]   * rsqrtf(vv[gc]   + EPSF);
                        float i1 = gg[gc+1] * rsqrtf(vv[gc+1] + EPSF);
                        v0 = v0*i0 + (bb[gc]   - mm[gc]  *i0);
                        v1 = v1*i1 + (bb[gc+1] - mm[gc+1]*i1);
                        v0 = v0 * __frcp_rn(1.f + __expf(-v0));
                        v1 = v1 * __frcp_rn(1.f + __expf(-v1));
                        *(__half2*)(crow + c) = __floats2half2_rn(v0, v1);
                    }
                }
            }
        }
    } else {
        // MODE 3: bn2 + residual, smem-transposed coalesced store to [b][c][hw]
        __syncthreads();
        float* stg = smemf + wid * (64*65);
#pragma unroll
        for (int ni = 0; ni < 8; ni++){
            const int gc = n0 + wn*64 + ni*8 + lc2;
            const float i0 = gg[gc]   * rsqrtf(vv[gc]   + EPSF);
            const float i1 = gg[gc+1] * rsqrtf(vv[gc+1] + EPSF);
            const float s0 = bb[gc]   - mm[gc]  *i0;
            const float s1 = bb[gc+1] - mm[gc+1]*i1;
#pragma unroll
            for (int mi = 0; mi < 4; mi++){
#pragma unroll
                for (int rr = 0; rr < 2; rr++){
                    const int lrow = mi*16 + lr + rr*8;
                    const int grow = m0 + wm*64 + lrow;
                    const float* rp = res + (size_t)grow*256 + gc;
                    stg[lrow*65 + ni*8 + lc2]     = d[mi][ni][rr*2+0]*i0 + s0 + rp[0];
                    stg[lrow*65 + ni*8 + lc2 + 1] = d[mi][ni][rr*2+1]*i1 + s1 + rp[1];
                }
            }
        }
        __syncwarp();
        const int pix0 = m0 + wm*64;
        const int bidx = pix0 / HW;
        const int pixl = pix0 - bidx*HW;
        float* ob = Cf + (size_t)bidx*C_*HW + pixl;
#pragma unroll
        for (int n = 0; n < 64; n++){
            const int gc = n0 + wn*64 + n;
            ob[(size_t)gc*HW + lane]      = stg[lane*65 + n];
            ob[(size_t)gc*HW + lane + 32] = stg[(lane+32)*65 + n];
        }
    }
}

// ---------------- transpose x [B][C][HW] -> xT half ----------------
__global__ __launch_bounds__(256) void transpose_k(const float* __restrict__ x,
                                                   __half* __restrict__ xT)
{
    __shared__ float t[32][33];
    const int b = blockIdx.z;
    const int hw0 = blockIdx.x * 32, c0 = blockIdx.y * 32;
    const int tx = threadIdx.x, ty = threadIdx.y;
#pragma unroll
    for (int i = 0; i < 4; i++){
        int c = c0 + ty + i*8;
        t[ty + i*8][tx] = x[(size_t)b*C_*HW + (size_t)c*HW + hw0 + tx];
    }
    __syncthreads();
#pragma unroll
    for (int i = 0; i < 4; i++){
        int hw = hw0 + ty + i*8;
        xT[(size_t)(b*HW + hw)*256 + c0 + tx] = __float2half_rn(t[tx][ty + i*8]);
    }
}

// ---------------- convert weights to half ----------------
__global__ __launch_bounds__(256) void convw_k(
    const float* __restrict__ qkvw, const float* __restrict__ projw,
    const float* __restrict__ w1, const float* __restrict__ w2, __half* __restrict__ gw)
{
    int i = blockIdx.x * 256 + threadIdx.x;
    float v;
    if (i < 196608)      v = qkvw[i];
    else if (i < 262144) v = projw[i - 196608];
    else if (i < 393216) v = w1[i - 262144];
    else                 v = w2[i - 393216];
    gw[i] = __float2half_rn(v);
}

// ---------------- fused attention + fc-mix + LayerNorm (half qkv) ----------------
__global__ __launch_bounds__(256) void attn_ln_k(
    const __half* __restrict__ qkv,
    const float* __restrict__ fcw, const float* __restrict__ fcb,
    const float* __restrict__ lng, const float* __restrict__ lnb,
    __half* __restrict__ y2)
{
    __shared__ float sOut[1024];      // [4 pixels][4 dil][64 ch]
    __shared__ float ssum[8][4], ssq[8][4];

    const int tid  = threadIdx.x;
    const int wid  = tid >> 5;
    const int lane = tid & 31;
    const int pp   = wid >> 1;
    const int dp   = wid & 1;
    const int dil  = dp*2 + (lane >> 4);
    const int c0   = (lane & 15) * 4;
    const int pix  = blockIdx.x * 4 + pp;
    const int b    = pix / HW;
    const int pixl = pix - b * HW;
    const int y    = pixl / Ww;
    const int x    = pixl - y * Ww;
    const int r    = 1 << dil;

    const __half* base = qkv + (size_t)b * HW * 768 + dil*64 + c0;

    int offs[9]; unsigned vm = 0;
#pragma unroll
    for (int j = 0; j < 9; j++){
        const int yy = y + (j/3 - 1) * r;
        const int xx = x + (j%3 - 1) * r;
        offs[j] = (yy*Ww + xx) * 768;
        if ((unsigned)yy < (unsigned)Hh && (unsigned)xx < (unsigned)Ww) vm |= 1u << j;
    }

    uint2 qu = *(const uint2*)(base + (size_t)pixl*768);
    const __half2 qh0 = *(__half2*)&qu.x;
    const __half2 qh1 = *(__half2*)&qu.y;

    float sc[9];
#pragma unroll
    for (int j = 0; j < 9; j++){
        float s = 0.f;
        if (vm & (1u << j)){
            uint2 ku = *(const uint2*)(base + offs[j] + 256);
            __half2 acc = __hmul2(qh0, *(__half2*)&ku.x);
            acc = __hfma2(qh1, *(__half2*)&ku.y, acc);
            s = __low2float(acc) + __high2float(acc);
        }
#pragma unroll
        for (int o = 8; o > 0; o >>= 1) s += __shfl_xor_sync(0xffffffffu, s, o);
        sc[j] = s * 0.125f;
    }

    float mx = sc[0];
#pragma unroll
    for (int j = 1; j < 9; j++) mx = fmaxf(mx, sc[j]);
    float p[9], sum = 0.f;
#pragma unroll
    for (int j = 0; j < 9; j++){ p[j] = __expf(sc[j] - mx); sum += p[j]; }
    const float inv = __frcp_rn(sum);

    float a0 = 0.f, a1 = 0.f, a2 = 0.f, a3 = 0.f;
#pragma unroll
    for (int j = 0; j < 9; j++){
        if (vm & (1u << j)){
            uint2 vu = *(const uint2*)(base + offs[j] + 512);
            const float2 v01 = __half22float2(*(__half2*)&vu.x);
            const float2 v23 = __half22float2(*(__half2*)&vu.y);
            a0 += p[j] * v01.x;
            a1 += p[j] * v01.y;
            a2 += p[j] * v23.x;
            a3 += p[j] * v23.y;
        }
    }
    *(float4*)(sOut + pp*256 + dil*64 + c0) = make_float4(a0*inv, a1*inv, a2*inv, a3*inv);
    __syncthreads();

    // fc mix + residual + LN(64): thread = (pixel px, channel c), all 4 slots
    const int px = tid >> 6;
    const int c  = tid & 63;
    const float* sp = sOut + px*256;
    const float s0 = sp[c], s1 = sp[64 + c], s2 = sp[128 + c], s3 = sp[192 + c];
    const float sv[4] = {s0, s1, s2, s3};
    float f[4], sm[4], sq[4];
#pragma unroll
    for (int t = 0; t < 4; t++){
        f[t] = fcw[t*4+0]*s0 + fcw[t*4+1]*s1 + fcw[t*4+2]*s2 + fcw[t*4+3]*s3
               + fcb[t] + sv[t];
        sm[t] = f[t]; sq[t] = f[t]*f[t];
    }
#pragma unroll
    for (int o = 16; o > 0; o >>= 1){
#pragma unroll
        for (int t = 0; t < 4; t++){
            sm[t] += __shfl_xor_sync(0xffffffffu, sm[t], o);
            sq[t] += __shfl_xor_sync(0xffffffffu, sq[t], o);
        }
    }
    if (lane == 0){
#pragma unroll
        for (int t = 0; t < 4; t++){ ssum[wid][t] = sm[t]; ssq[wid][t] = sq[t]; }
    }
    __syncthreads();
    const float lg = lng[c], lb = lnb[c];
    __half* yo = y2 + (size_t)(blockIdx.x*4 + px)*256 + c;
#pragma unroll
    for (int t = 0; t < 4; t++){
        const float tot  = ssum[px*2][t] + ssum[px*2+1][t];
        const float totq = ssq[px*2][t]  + ssq[px*2+1][t];
        const float mu  = tot * (1.f/64.f);
        const float var = totq * (1.f/64.f) - mu*mu;
        yo[t*64] = __float2half_rn((f[t] - mu) * rsqrtf(var + EPSF) * lg + lb);
    }
}

// ---------------- launch ----------------
extern "C" void kernel_launch(void* const* d_in, const int* in_sizes, int n_in,
                              void* d_out, int out_size)
{
    const float* x      = (const float*)d_in[0];
    const float* qkv_w  = (const float*)d_in[1];
    const float* qkv_b  = (const float*)d_in[2];
    const float* fc_w   = (const float*)d_in[3];
    const float* fc_b   = (const float*)d_in[4];
    const float* ln_g   = (const float*)d_in[5];
    const float* ln_b   = (const float*)d_in[6];
    const float* proj_w = (const float*)d_in[7];
    const float* proj_b = (const float*)d_in[8];
    const float* w1     = (const float*)d_in[9];
    const float* bn1_g  = (const float*)d_in[10];
    const float* bn1_b  = (const float*)d_in[11];
    const float* bn1_m  = (const float*)d_in[12];
    const float* bn1_v  = (const float*)d_in[13];
    const float* w2     = (const float*)d_in[14];
    const float* bn2_g  = (const float*)d_in[15];
    const float* bn2_b  = (const float*)d_in[16];
    const float* bn2_m  = (const float*)d_in[17];
    const float* bn2_v  = (const float*)d_in[18];
    float* out = (float*)d_out;

    __half *xT, *qkv, *y2, *x1h, *hb, *gw;
    float *x1f;
    cudaGetSymbolAddress((void**)&xT,  g_xT);
    cudaGetSymbolAddress((void**)&qkv, g_qkv);
    cudaGetSymbolAddress((void**)&y2,  g_y2);
    cudaGetSymbolAddress((void**)&x1h, g_x1h);
    cudaGetSymbolAddress((void**)&x1f, g_x1f);
    cudaGetSymbolAddress((void**)&hb,  g_h);
    cudaGetSymbolAddress((void**)&gw,  g_w);

    cudaFuncSetAttribute(gemm_mma<0>, cudaFuncAttributeMaxDynamicSharedMemorySize, SMEM_BYTES);
    cudaFuncSetAttribute(gemm_mma<1>, cudaFuncAttributeMaxDynamicSharedMemorySize, SMEM_BYTES);
    cudaFuncSetAttribute(gemm_mma<2>, cudaFuncAttributeMaxDynamicSharedMemorySize, SMEM_BYTES);
    cudaFuncSetAttribute(gemm_mma<3>, cudaFuncAttributeMaxDynamicSharedMemorySize, SMEM_BYTES);

    convw_k<<<2048, 256>>>(qkv_w, proj_w, w1, w2, gw);
    transpose_k<<<dim3(HW/32, C_/32, B_), dim3(32, 8)>>>(x, xT);

    // 1) qkv = xT @ qkv_w^T + b : [51200][768] half
    gemm_mma<0><<<dim3(6, 400), 128, SMEM_BYTES>>>(
        xT, gw, qkv, nullptr, 256, 768, qkv_b, nullptr, nullptr, nullptr, nullptr, nullptr);

    // 2+3) attention + fc mix + LN (fused) -> y2 half
    attn_ln_k<<<NPIX/4, 256>>>(qkv, fc_w, fc_b, ln_g, ln_b, y2);

    // 4) x1 = y2 @ proj_w^T + proj_b + x -> x1h (half) / x1f (float)
    gemm_mma<1><<<dim3(2, 400), 128, SMEM_BYTES>>>(
        y2, gw + 196608, x1h, x1f, 256, 256, proj_b, x, nullptr, nullptr, nullptr, nullptr);

    // 5) h = silu(bn1(x1 @ w1^T)) : [51200][512] half
    gemm_mma<2><<<dim3(4, 400), 128, SMEM_BYTES>>>(
        x1h, gw + 262144, hb, nullptr, 256, 512, nullptr, nullptr, bn1_g, bn1_b, bn1_m, bn1_v);

    // 6) out = x1 + bn2(h @ w2^T) -> [B][C][HW] float
    gemm_mma<3><<<dim3(2, 400), 128, SMEM_BYTES>>>(
        hb, gw + 393216, nullptr, out, 512, 256, nullptr, x1f, bn2_g, bn2_b, bn2_m, bn2_v);
}

// round 10
// speedup vs baseline: 1.0724x; 1.0724x over previous
#include <cuda_runtime.h>
#include <cuda_fp16.h>
#include <cstdint>
#include <math.h>

#define B_  8
#define C_  256
#define Hh  80
#define Ww  80
#define HW  6400
#define NPIX 51200
#define EPSF 1e-5f

#define KC 32
#define STAGES 4
#define TSTRH 40                 // smem row stride in halfs (80B): LDSM conflict-free
#define ST_B (128*TSTRH*2)       // 10240 B per operand stage
#define SMEM_BYTES (STAGES*2*ST_B)   // 81920 B per CTA

// ---------------- scratch ----------------
__device__ __half g_xT [(size_t)NPIX*256];
__device__ __half g_qkv[(size_t)NPIX*768];
__device__ __half g_y2 [(size_t)NPIX*256];
__device__ __half g_x1h[(size_t)NPIX*256];
__device__ float  g_x1f[(size_t)NPIX*256];
__device__ __half g_h  [(size_t)NPIX*512];
__device__ __half g_w  [524288];

// ---------------- helpers ----------------
__device__ __forceinline__ uint32_t s2u(const void* p){
    uint32_t a; asm("{ .reg .u64 t; cvta.to.shared.u64 t, %1; cvt.u32.u64 %0, t; }" : "=r"(a) : "l"(p)); return a;
}
#define CPA16(d,s) asm volatile("cp.async.cg.shared.global [%0], [%1], 16;" :: "r"(d), "l"(s))
#define CPCOMMIT() asm volatile("cp.async.commit_group;" ::: "memory")
#define CPWAIT(n)  asm volatile("cp.async.wait_group %0;" :: "n"(n) : "memory")
#define LDSM4(r0,r1,r2,r3,a) \
    asm volatile("ldmatrix.sync.aligned.m8n8.x4.shared.b16 {%0,%1,%2,%3}, [%4];" \
        : "=r"(r0), "=r"(r1), "=r"(r2), "=r"(r3) : "r"(a))

__device__ __forceinline__ void mma16(float* d, const uint32_t* a, uint32_t b0, uint32_t b1){
    asm volatile("mma.sync.aligned.m16n8k16.row.col.f32.f16.f16.f32 "
        "{%0,%1,%2,%3}, {%4,%5,%6,%7}, {%8,%9}, {%0,%1,%2,%3};"
        : "+f"(d[0]), "+f"(d[1]), "+f"(d[2]), "+f"(d[3])
        : "r"(a[0]), "r"(a[1]), "r"(a[2]), "r"(a[3]), "r"(b0), "r"(b1));
}

// ---------------- fp16 mma.sync GEMM, 128x128 tile, 8 warps (64x32 warp tile) ----------------
// MODE 0: Ch = acc + bias[n]                      -> qkv half (Cstride 768)
// MODE 1: Ch = half(acc+bias+resx), Cf = full     -> x1h / x1f  (resx = x[b][c][hw] fp32)
// MODE 2: Ch = half(silu(acc*sc+sh))              -> h half (Cstride 512)
// MODE 3: Cf = acc*sc+sh + res -> out[b][n][pixl] (smem-staged transposed store; res fp32)
template<int MODE>
__global__ __launch_bounds__(256, 2) void gemm_mma(
    const __half* __restrict__ A, const __half* __restrict__ Bw,
    __half* __restrict__ Ch, float* __restrict__ Cf, int Ktot, int Cstride,
    const float* __restrict__ bias, const float* __restrict__ res,
    const float* __restrict__ gg, const float* __restrict__ bb,
    const float* __restrict__ mm, const float* __restrict__ vv)
{
    extern __shared__ float smemf[];
    const uint32_t smem_b = s2u(smemf);

    const int tid  = threadIdx.x;
    const int wid  = tid >> 5;
    const int lane = tid & 31;
    const int wm   = wid & 1;         // 2 warps in M (64 rows)
    const int wn   = wid >> 1;        // 4 warps in N (32 cols)
    const int lr   = lane >> 2;
    const int lc   = lane & 3;
    const int m0   = blockIdx.y * 128;
    const int n0   = blockIdx.x * 128;

    // LDSM per-thread byte offsets within a stage
    const uint32_t aoff = (uint32_t)(((wm*64 + ((lane>>3)&1)*8 + (lane&7))*TSTRH + (lane>>4)*8) * 2);
    const uint32_t boff = (uint32_t)(((wn*32 + (lane>>4)*8 + (lane&7))*TSTRH + ((lane>>3)&1)*8) * 2);

    float d[4][4][4];
#pragma unroll
    for (int i = 0; i < 4; i++)
#pragma unroll
        for (int j = 0; j < 4; j++)
#pragma unroll
            for (int e = 0; e < 4; e++) d[i][j][e] = 0.f;

    const int nch = Ktot / KC;

    auto load = [&](int cc){
        const int s = cc % STAGES;
        const __half* Ab = A + (size_t)m0 * Ktot + cc*KC;
        const uint32_t da = smem_b + (2*s)*ST_B;
#pragma unroll
        for (int t = 0; t < 2; t++){
            int i = tid + t*256;
            int r = i >> 2, c = i & 3;
            CPA16(da + r*TSTRH*2 + c*16, (const void*)(Ab + (size_t)r*Ktot + c*8));
        }
        const __half* Bb = Bw + (size_t)n0 * Ktot + cc*KC;
        const uint32_t db = smem_b + (2*s+1)*ST_B;
#pragma unroll
        for (int t = 0; t < 2; t++){
            int i = tid + t*256;
            int r = i >> 2, c = i & 3;
            CPA16(db + r*TSTRH*2 + c*16, (const void*)(Bb + (size_t)r*Ktot + c*8));
        }
        CPCOMMIT();
    };

    load(0); load(1); load(2);

    for (int cc = 0; cc < nch; cc++){
        const int rem = nch - 1 - cc;
        if (rem >= 2)      CPWAIT(2);
        else if (rem == 1) CPWAIT(1);
        else               CPWAIT(0);
        __syncthreads();
        if (cc + 3 < nch) load(cc + 3);

        const int s = cc % STAGES;
        const uint32_t aBase = smem_b + (2*s)*ST_B + aoff;
        const uint32_t bBase = smem_b + (2*s+1)*ST_B + boff;
#pragma unroll
        for (int kk = 0; kk < 2; kk++){
            uint32_t a[4][4], bf[2][4];
#pragma unroll
            for (int mi = 0; mi < 4; mi++)
                LDSM4(a[mi][0], a[mi][1], a[mi][2], a[mi][3],
                      aBase + mi*(16*TSTRH*2) + kk*32);
#pragma unroll
            for (int np = 0; np < 2; np++)
                LDSM4(bf[np][0], bf[np][1], bf[np][2], bf[np][3],
                      bBase + np*(16*TSTRH*2) + kk*32);
#pragma unroll
            for (int np = 0; np < 2; np++)
#pragma unroll
                for (int mi = 0; mi < 4; mi++){
                    mma16(d[mi][2*np],   a[mi], bf[np][0], bf[np][1]);
                    mma16(d[mi][2*np+1], a[mi], bf[np][2], bf[np][3]);
                }
        }
    }

    // ---------------- epilogue ----------------
    const int lc2 = lc * 2;

    if (MODE != 3){
        const int bidx  = (MODE == 1) ? m0 / HW : 0;
        const int pixl0 = (MODE == 1) ? m0 - bidx*HW : 0;
        const float* xb = (MODE == 1) ? res + (size_t)bidx*C_*HW : (const float*)0;
#pragma unroll
        for (int mi = 0; mi < 4; mi++){
#pragma unroll
            for (int rr = 0; rr < 2; rr++){
                const int rl = wm*64 + mi*16 + lr + rr*8;
                const int r  = m0 + rl;
                __half* crow = Ch + (size_t)r*Cstride + n0 + wn*32;
                float* crow2 = (MODE == 1) ? Cf + (size_t)r*256 + n0 + wn*32 : (float*)0;
                const int pixl = pixl0 + rl;
#pragma unroll
                for (int ni = 0; ni < 4; ni++){
                    const int c = ni*8 + lc2;
                    const int gc = n0 + wn*32 + c;
                    float v0 = d[mi][ni][rr*2+0];
                    float v1 = d[mi][ni][rr*2+1];
                    if (MODE == 0){
                        v0 += bias[gc]; v1 += bias[gc+1];
                        *(__half2*)(crow + c) = __floats2half2_rn(v0, v1);
                    } else if (MODE == 1){
                        v0 += bias[gc]   + xb[(size_t)gc*HW + pixl];
                        v1 += bias[gc+1] + xb[(size_t)(gc+1)*HW + pixl];
                        *(float2*)(crow2 + c) = make_float2(v0, v1);
                        *(__half2*)(crow + c) = __floats2half2_rn(v0, v1);
                    } else { // MODE 2
                        float i0 = gg[gc]   * rsqrtf(vv[gc]   + EPSF);
                        float i1 = gg[gc+1] * rsqrtf(vv[gc+1] + EPSF);
                        v0 = v0*i0 + (bb[gc]   - mm[gc]  *i0);
                        v1 = v1*i1 + (bb[gc+1] - mm[gc+1]*i1);
                        v0 = v0 * __frcp_rn(1.f + __expf(-v0));
                        v1 = v1 * __frcp_rn(1.f + __expf(-v1));
                        *(__half2*)(crow + c) = __floats2half2_rn(v0, v1);
                    }
                }
            }
        }
    } else {
        // MODE 3: bn2 + residual, smem-transposed coalesced store to [b][c][hw]
        __syncthreads();
        float* stg = smemf + wid * (64*33);
#pragma unroll
        for (int ni = 0; ni < 4; ni++){
            const int gc = n0 + wn*32 + ni*8 + lc2;
            const float i0 = gg[gc]   * rsqrtf(vv[gc]   + EPSF);
            const float i1 = gg[gc+1] * rsqrtf(vv[gc+1] + EPSF);
            const float s0 = bb[gc]   - mm[gc]  *i0;
            const float s1 = bb[gc+1] - mm[gc+1]*i1;
#pragma unroll
            for (int mi = 0; mi < 4; mi++){
#pragma unroll
                for (int rr = 0; rr < 2; rr++){
                    const int lrow = mi*16 + lr + rr*8;
                    const int grow = m0 + wm*64 + lrow;
                    const float* rp = res + (size_t)grow*256 + gc;
                    stg[lrow*33 + ni*8 + lc2]     = d[mi][ni][rr*2+0]*i0 + s0 + rp[0];
                    stg[lrow*33 + ni*8 + lc2 + 1] = d[mi][ni][rr*2+1]*i1 + s1 + rp[1];
                }
            }
        }
        __syncwarp();
        const int pix0 = m0 + wm*64;
        const int bidx = pix0 / HW;
        const int pixl = pix0 - bidx*HW;
        float* ob = Cf + (size_t)bidx*C_*HW + pixl;
#pragma unroll
        for (int n = 0; n < 32; n++){
            const int gc = n0 + wn*32 + n;
            ob[(size_t)gc*HW + lane]      = stg[lane*33 + n];
            ob[(size_t)gc*HW + lane + 32] = stg[(lane+32)*33 + n];
        }
    }
}

// ---------------- transpose x [B][C][HW] -> xT half ----------------
__global__ __launch_bounds__(256) void transpose_k(const float* __restrict__ x,
                                                   __half* __restrict__ xT)
{
    __shared__ float t[32][33];
    const int b = blockIdx.z;
    const int hw0 = blockIdx.x * 32, c0 = blockIdx.y * 32;
    const int tx = threadIdx.x, ty = threadIdx.y;
#pragma unroll
    for (int i = 0; i < 4; i++){
        int c = c0 + ty + i*8;
        t[ty + i*8][tx] = x[(size_t)b*C_*HW + (size_t)c*HW + hw0 + tx];
    }
    __syncthreads();
#pragma unroll
    for (int i = 0; i < 4; i++){
        int hw = hw0 + ty + i*8;
        xT[(size_t)(b*HW + hw)*256 + c0 + tx] = __float2half_rn(t[tx][ty + i*8]);
    }
}

// ---------------- convert weights to half ----------------
__global__ __launch_bounds__(256) void convw_k(
    const float* __restrict__ qkvw, const float* __restrict__ projw,
    const float* __restrict__ w1, const float* __restrict__ w2, __half* __restrict__ gw)
{
    int i = blockIdx.x * 256 + threadIdx.x;
    float v;
    if (i < 196608)      v = qkvw[i];
    else if (i < 262144) v = projw[i - 196608];
    else if (i < 393216) v = w1[i - 262144];
    else                 v = w2[i - 393216];
    gw[i] = __float2half_rn(v);
}

// ---------------- fused attention + fc-mix + LayerNorm (half qkv, single-pass LN) ----------------
__global__ __launch_bounds__(256) void attn_ln_k(
    const __half* __restrict__ qkv,
    const float* __restrict__ fcw, const float* __restrict__ fcb,
    const float* __restrict__ lng, const float* __restrict__ lnb,
    __half* __restrict__ y2)
{
    __shared__ float sOut[1024];      // [4 pixels][4 dil][64 ch]
    __shared__ float ssum[8][4], ssq[8][4];

    const int tid  = threadIdx.x;
    const int wid  = tid >> 5;
    const int lane = tid & 31;
    const int pp   = wid >> 1;
    const int dp   = wid & 1;
    const int dil  = dp*2 + (lane >> 4);
    const int c0   = (lane & 15) * 4;
    const int pix  = blockIdx.x * 4 + pp;
    const int b    = pix / HW;
    const int pixl = pix - b * HW;
    const int y    = pixl / Ww;
    const int x    = pixl - y * Ww;
    const int r    = 1 << dil;

    const __half* base = qkv + (size_t)b * HW * 768 + dil*64 + c0;

    int offs[9]; unsigned vm = 0;
#pragma unroll
    for (int j = 0; j < 9; j++){
        const int yy = y + (j/3 - 1) * r;
        const int xx = x + (j%3 - 1) * r;
        offs[j] = (yy*Ww + xx) * 768;
        if ((unsigned)yy < (unsigned)Hh && (unsigned)xx < (unsigned)Ww) vm |= 1u << j;
    }

    uint2 qu = *(const uint2*)(base + (size_t)pixl*768);
    const __half2 qh0 = *(__half2*)&qu.x;
    const __half2 qh1 = *(__half2*)&qu.y;

    float sc[9];
#pragma unroll
    for (int j = 0; j < 9; j++){
        float s = 0.f;
        if (vm & (1u << j)){
            uint2 ku = *(const uint2*)(base + offs[j] + 256);
            __half2 acc = __hmul2(qh0, *(__half2*)&ku.x);
            acc = __hfma2(qh1, *(__half2*)&ku.y, acc);
            s = __low2float(acc) + __high2float(acc);
        }
#pragma unroll
        for (int o = 8; o > 0; o >>= 1) s += __shfl_xor_sync(0xffffffffu, s, o);
        sc[j] = s * 0.125f;
    }

    float mx = sc[0];
#pragma unroll
    for (int j = 1; j < 9; j++) mx = fmaxf(mx, sc[j]);
    float p[9], sum = 0.f;
#pragma unroll
    for (int j = 0; j < 9; j++){ p[j] = __expf(sc[j] - mx); sum += p[j]; }
    const float inv = __frcp_rn(sum);

    float a0 = 0.f, a1 = 0.f, a2 = 0.f, a3 = 0.f;
#pragma unroll
    for (int j = 0; j < 9; j++){
        if (vm & (1u << j)){
            uint2 vu = *(const uint2*)(base + offs[j] + 512);
            const float2 v01 = __half22float2(*(__half2*)&vu.x);
            const float2 v23 = __half22float2(*(__half2*)&vu.y);
            a0 += p[j] * v01.x;
            a1 += p[j] * v01.y;
            a2 += p[j] * v23.x;
            a3 += p[j] * v23.y;
        }
    }
    *(float4*)(sOut + pp*256 + dil*64 + c0) = make_float4(a0*inv, a1*inv, a2*inv, a3*inv);
    __syncthreads();

    // fc mix + residual + LN(64): thread = (pixel px, channel c), all 4 slots
    const int px = tid >> 6;
    const int c  = tid & 63;
    const float* sp = sOut + px*256;
    const float s0 = sp[c], s1 = sp[64 + c], s2 = sp[128 + c], s3 = sp[192 + c];
    const float sv[4] = {s0, s1, s2, s3};
    float f[4], sm[4], sq[4];
#pragma unroll
    for (int t = 0; t < 4; t++){
        f[t] = fcw[t*4+0]*s0 + fcw[t*4+1]*s1 + fcw[t*4+2]*s2 + fcw[t*4+3]*s3
               + fcb[t] + sv[t];
        sm[t] = f[t]; sq[t] = f[t]*f[t];
    }
#pragma unroll
    for (int o = 16; o > 0; o >>= 1){
#pragma unroll
        for (int t = 0; t < 4; t++){
            sm[t] += __shfl_xor_sync(0xffffffffu, sm[t], o);
            sq[t] += __shfl_xor_sync(0xffffffffu, sq[t], o);
        }
    }
    if (lane == 0){
#pragma unroll
        for (int t = 0; t < 4; t++){ ssum[wid][t] = sm[t]; ssq[wid][t] = sq[t]; }
    }
    __syncthreads();
    const float lg = lng[c], lb = lnb[c];
    __half* yo = y2 + (size_t)(blockIdx.x*4 + px)*256 + c;
#pragma unroll
    for (int t = 0; t < 4; t++){
        const float tot  = ssum[px*2][t] + ssum[px*2+1][t];
        const float totq = ssq[px*2][t]  + ssq[px*2+1][t];
        const float mu  = tot * (1.f/64.f);
        const float var = totq * (1.f/64.f) - mu*mu;
        yo[t*64] = __float2half_rn((f[t] - mu) * rsqrtf(var + EPSF) * lg + lb);
    }
}

// ---------------- launch ----------------
extern "C" void kernel_launch(void* const* d_in, const int* in_sizes, int n_in,
                              void* d_out, int out_size)
{
    const float* x      = (const float*)d_in[0];
    const float* qkv_w  = (const float*)d_in[1];
    const float* qkv_b  = (const float*)d_in[2];
    const float* fc_w   = (const float*)d_in[3];
    const float* fc_b   = (const float*)d_in[4];
    const float* ln_g   = (const float*)d_in[5];
    const float* ln_b   = (const float*)d_in[6];
    const float* proj_w = (const float*)d_in[7];
    const float* proj_b = (const float*)d_in[8];
    const float* w1     = (const float*)d_in[9];
    const float* bn1_g  = (const float*)d_in[10];
    const float* bn1_b  = (const float*)d_in[11];
    const float* bn1_m  = (const float*)d_in[12];
    const float* bn1_v  = (const float*)d_in[13];
    const float* w2     = (const float*)d_in[14];
    const float* bn2_g  = (const float*)d_in[15];
    const float* bn2_b  = (const float*)d_in[16];
    const float* bn2_m  = (const float*)d_in[17];
    const float* bn2_v  = (const float*)d_in[18];
    float* out = (float*)d_out;

    __half *xT, *qkv, *y2, *x1h, *hb, *gw;
    float *x1f;
    cudaGetSymbolAddress((void**)&xT,  g_xT);
    cudaGetSymbolAddress((void**)&qkv, g_qkv);
    cudaGetSymbolAddress((void**)&y2,  g_y2);
    cudaGetSymbolAddress((void**)&x1h, g_x1h);
    cudaGetSymbolAddress((void**)&x1f, g_x1f);
    cudaGetSymbolAddress((void**)&hb,  g_h);
    cudaGetSymbolAddress((void**)&gw,  g_w);

    cudaFuncSetAttribute(gemm_mma<0>, cudaFuncAttributeMaxDynamicSharedMemorySize, SMEM_BYTES);
    cudaFuncSetAttribute(gemm_mma<1>, cudaFuncAttributeMaxDynamicSharedMemorySize, SMEM_BYTES);
    cudaFuncSetAttribute(gemm_mma<2>, cudaFuncAttributeMaxDynamicSharedMemorySize, SMEM_BYTES);
    cudaFuncSetAttribute(gemm_mma<3>, cudaFuncAttributeMaxDynamicSharedMemorySize, SMEM_BYTES);

    convw_k<<<2048, 256>>>(qkv_w, proj_w, w1, w2, gw);
    transpose_k<<<dim3(HW/32, C_/32, B_), dim3(32, 8)>>>(x, xT);

    // 1) qkv = xT @ qkv_w^T + b : [51200][768] half
    gemm_mma<0><<<dim3(6, 400), 256, SMEM_BYTES>>>(
        xT, gw, qkv, nullptr, 256, 768, qkv_b, nullptr, nullptr, nullptr, nullptr, nullptr);

    // 2+3) attention + fc mix + LN (fused) -> y2 half
    attn_ln_k<<<NPIX/4, 256>>>(qkv, fc_w, fc_b, ln_g, ln_b, y2);

    // 4) x1 = y2 @ proj_w^T + proj_b + x -> x1h (half) / x1f (float)
    gemm_mma<1><<<dim3(2, 400), 256, SMEM_BYTES>>>(
        y2, gw + 196608, x1h, x1f, 256, 256, proj_b, x, nullptr, nullptr, nullptr, nullptr);

    // 5) h = silu(bn1(x1 @ w1^T)) : [51200][512] half
    gemm_mma<2><<<dim3(4, 400), 256, SMEM_BYTES>>>(
        x1h, gw + 262144, hb, nullptr, 256, 512, nullptr, nullptr, bn1_g, bn1_b, bn1_m, bn1_v);

    // 6) out = x1 + bn2(h @ w2^T) -> [B][C][HW] float
    gemm_mma<3><<<dim3(2, 400), 256, SMEM_BYTES>>>(
        hb, gw + 393216, nullptr, out, 512, 256, nullptr, x1f, bn2_g, bn2_b, bn2_m, bn2_v);
}

// round 11
// speedup vs baseline: 1.1261x; 1.0501x over previous
#include <cuda_runtime.h>
#include <cuda_fp16.h>
#include <cstdint>
#include <math.h>

#define B_  8
#define C_  256
#define Hh  80
#define Ww  80
#define HW  6400
#define NPIX 51200
#define EPSF 1e-5f

#define KC 64
#define STAGES 3
#define TSTRH 72                 // smem row stride in halfs (144B): LDSM conflict-free
#define ST_B (128*TSTRH*2)       // 18432 B per operand stage
#define SMEM_BYTES (STAGES*2*ST_B)   // 110592 B per CTA

// ---------------- scratch ----------------
__device__ __half g_xT [(size_t)NPIX*256];
__device__ __half g_qkv[(size_t)NPIX*768];
__device__ __half g_y2 [(size_t)NPIX*256];
__device__ __half g_x1h[(size_t)NPIX*256];
__device__ float  g_x1f[(size_t)NPIX*256];
__device__ __half g_h  [(size_t)NPIX*512];
__device__ __half g_w  [524288];

// ---------------- helpers ----------------
__device__ __forceinline__ uint32_t s2u(const void* p){
    uint32_t a; asm("{ .reg .u64 t; cvta.to.shared.u64 t, %1; cvt.u32.u64 %0, t; }" : "=r"(a) : "l"(p)); return a;
}
#define CPA16(d,s) asm volatile("cp.async.cg.shared.global [%0], [%1], 16;" :: "r"(d), "l"(s))
#define CPCOMMIT() asm volatile("cp.async.commit_group;" ::: "memory")
#define CPWAIT(n)  asm volatile("cp.async.wait_group %0;" :: "n"(n) : "memory")
#define LDSM4(r0,r1,r2,r3,a) \
    asm volatile("ldmatrix.sync.aligned.m8n8.x4.shared.b16 {%0,%1,%2,%3}, [%4];" \
        : "=r"(r0), "=r"(r1), "=r"(r2), "=r"(r3) : "r"(a))

__device__ __forceinline__ void mma16(float* d, const uint32_t* a, uint32_t b0, uint32_t b1){
    asm volatile("mma.sync.aligned.m16n8k16.row.col.f32.f16.f16.f32 "
        "{%0,%1,%2,%3}, {%4,%5,%6,%7}, {%8,%9}, {%0,%1,%2,%3};"
        : "+f"(d[0]), "+f"(d[1]), "+f"(d[2]), "+f"(d[3])
        : "r"(a[0]), "r"(a[1]), "r"(a[2]), "r"(a[3]), "r"(b0), "r"(b1));
}

// ---------------- fp16 mma.sync GEMM, 128x128 tile, 8 warps, KC=64, 3 stages ----------------
// MODE 0: Ch = acc + bias[n]                      -> qkv half (Cstride 768)
// MODE 1: Ch = half(acc+bias+resx), Cf = full     -> x1h / x1f  (resx = x[b][c][hw] fp32)
// MODE 2: Ch = half(silu(acc*sc+sh))              -> h half (Cstride 512)
// MODE 3: Cf = acc*sc+sh + res -> out[b][n][pixl] (smem-staged transposed store; res fp32)
template<int MODE>
__global__ __launch_bounds__(256, 2) void gemm_mma(
    const __half* __restrict__ A, const __half* __restrict__ Bw,
    __half* __restrict__ Ch, float* __restrict__ Cf, int Ktot, int Cstride,
    const float* __restrict__ bias, const float* __restrict__ res,
    const float* __restrict__ gg, const float* __restrict__ bb,
    const float* __restrict__ mm, const float* __restrict__ vv)
{
    extern __shared__ float smemf[];
    const uint32_t smem_b = s2u(smemf);

    const int tid  = threadIdx.x;
    const int wid  = tid >> 5;
    const int lane = tid & 31;
    const int wm   = wid & 1;         // 2 warps in M (64 rows)
    const int wn   = wid >> 1;        // 4 warps in N (32 cols)
    const int lr   = lane >> 2;
    const int lc   = lane & 3;
    const int m0   = blockIdx.y * 128;
    const int n0   = blockIdx.x * 128;

    const uint32_t aoff = (uint32_t)(((wm*64 + ((lane>>3)&1)*8 + (lane&7))*TSTRH + (lane>>4)*8) * 2);
    const uint32_t boff = (uint32_t)(((wn*32 + (lane>>4)*8 + (lane&7))*TSTRH + ((lane>>3)&1)*8) * 2);

    float d[4][4][4];
#pragma unroll
    for (int i = 0; i < 4; i++)
#pragma unroll
        for (int j = 0; j < 4; j++)
#pragma unroll
            for (int e = 0; e < 4; e++) d[i][j][e] = 0.f;

    const int nch = Ktot / KC;

    auto load = [&](int cc){
        const int s = cc % STAGES;
        const __half* Ab = A + (size_t)m0 * Ktot + cc*KC;
        const uint32_t da = smem_b + (2*s)*ST_B;
#pragma unroll
        for (int t = 0; t < 4; t++){
            int i = tid + t*256;
            int r = i >> 3, c = i & 7;
            CPA16(da + r*TSTRH*2 + c*16, (const void*)(Ab + (size_t)r*Ktot + c*8));
        }
        const __half* Bb = Bw + (size_t)n0 * Ktot + cc*KC;
        const uint32_t db = smem_b + (2*s+1)*ST_B;
#pragma unroll
        for (int t = 0; t < 4; t++){
            int i = tid + t*256;
            int r = i >> 3, c = i & 7;
            CPA16(db + r*TSTRH*2 + c*16, (const void*)(Bb + (size_t)r*Ktot + c*8));
        }
        CPCOMMIT();
    };

    load(0); load(1);

    for (int cc = 0; cc < nch; cc++){
        const int rem = nch - 1 - cc;
        if (rem >= 1) CPWAIT(1);
        else          CPWAIT(0);
        __syncthreads();
        if (cc + 2 < nch) load(cc + 2);

        const int s = cc % STAGES;
        const uint32_t aBase = smem_b + (2*s)*ST_B + aoff;
        const uint32_t bBase = smem_b + (2*s+1)*ST_B + boff;
#pragma unroll
        for (int kk = 0; kk < 4; kk++){
            uint32_t a[4][4], bf[2][4];
#pragma unroll
            for (int mi = 0; mi < 4; mi++)
                LDSM4(a[mi][0], a[mi][1], a[mi][2], a[mi][3],
                      aBase + mi*(16*TSTRH*2) + kk*32);
#pragma unroll
            for (int np = 0; np < 2; np++)
                LDSM4(bf[np][0], bf[np][1], bf[np][2], bf[np][3],
                      bBase + np*(16*TSTRH*2) + kk*32);
#pragma unroll
            for (int np = 0; np < 2; np++)
#pragma unroll
                for (int mi = 0; mi < 4; mi++){
                    mma16(d[mi][2*np],   a[mi], bf[np][0], bf[np][1]);
                    mma16(d[mi][2*np+1], a[mi], bf[np][2], bf[np][3]);
                }
        }
    }

    // ---------------- epilogue ----------------
    const int lc2 = lc * 2;

    if (MODE != 3){
        const int bidx  = (MODE == 1) ? m0 / HW : 0;
        const int pixl0 = (MODE == 1) ? m0 - bidx*HW : 0;
        const float* xb = (MODE == 1) ? res + (size_t)bidx*C_*HW : (const float*)0;
#pragma unroll
        for (int mi = 0; mi < 4; mi++){
#pragma unroll
            for (int rr = 0; rr < 2; rr++){
                const int rl = wm*64 + mi*16 + lr + rr*8;
                const int r  = m0 + rl;
                __half* crow = Ch + (size_t)r*Cstride + n0 + wn*32;
                float* crow2 = (MODE == 1) ? Cf + (size_t)r*256 + n0 + wn*32 : (float*)0;
                const int pixl = pixl0 + rl;
#pragma unroll
                for (int ni = 0; ni < 4; ni++){
                    const int c = ni*8 + lc2;
                    const int gc = n0 + wn*32 + c;
                    float v0 = d[mi][ni][rr*2+0];
                    float v1 = d[mi][ni][rr*2+1];
                    if (MODE == 0){
                        v0 += bias[gc]; v1 += bias[gc+1];
                        *(__half2*)(crow + c) = __floats2half2_rn(v0, v1);
                    } else if (MODE == 1){
                        v0 += bias[gc]   + xb[(size_t)gc*HW + pixl];
                        v1 += bias[gc+1] + xb[(size_t)(gc+1)*HW + pixl];
                        *(float2*)(crow2 + c) = make_float2(v0, v1);
                        *(__half2*)(crow + c) = __floats2half2_rn(v0, v1);
                    } else { // MODE 2
                        float i0 = gg[gc]   * rsqrtf(vv[gc]   + EPSF);
                        float i1 = gg[gc+1] * rsqrtf(vv[gc+1] + EPSF);
                        v0 = v0*i0 + (bb[gc]   - mm[gc]  *i0);
                        v1 = v1*i1 + (bb[gc+1] - mm[gc+1]*i1);
                        v0 = v0 * __frcp_rn(1.f + __expf(-v0));
                        v1 = v1 * __frcp_rn(1.f + __expf(-v1));
                        *(__half2*)(crow + c) = __floats2half2_rn(v0, v1);
                    }
                }
            }
        }
    } else {
        // MODE 3: bn2 + residual, smem-transposed coalesced store to [b][c][hw]
        __syncthreads();
        float* stg = smemf + wid * (64*33);
#pragma unroll
        for (int ni = 0; ni < 4; ni++){
            const int gc = n0 + wn*32 + ni*8 + lc2;
            const float i0 = gg[gc]   * rsqrtf(vv[gc]   + EPSF);
            const float i1 = gg[gc+1] * rsqrtf(vv[gc+1] + EPSF);
            const float s0 = bb[gc]   - mm[gc]  *i0;
            const float s1 = bb[gc+1] - mm[gc+1]*i1;
#pragma unroll
            for (int mi = 0; mi < 4; mi++){
#pragma unroll
                for (int rr = 0; rr < 2; rr++){
                    const int lrow = mi*16 + lr + rr*8;
                    const int grow = m0 + wm*64 + lrow;
                    const float* rp = res + (size_t)grow*256 + gc;
                    stg[lrow*33 + ni*8 + lc2]     = d[mi][ni][rr*2+0]*i0 + s0 + rp[0];
                    stg[lrow*33 + ni*8 + lc2 + 1] = d[mi][ni][rr*2+1]*i1 + s1 + rp[1];
                }
            }
        }
        __syncwarp();
        const int pix0 = m0 + wm*64;
        const int bidx = pix0 / HW;
        const int pixl = pix0 - bidx*HW;
        float* ob = Cf + (size_t)bidx*C_*HW + pixl;
#pragma unroll
        for (int n = 0; n < 32; n++){
            const int gc = n0 + wn*32 + n;
            ob[(size_t)gc*HW + lane]      = stg[lane*33 + n];
            ob[(size_t)gc*HW + lane + 32] = stg[(lane+32)*33 + n];
        }
    }
}

// ---------------- transpose x [B][C][HW] -> xT half ----------------
__global__ __launch_bounds__(256) void transpose_k(const float* __restrict__ x,
                                                   __half* __restrict__ xT)
{
    __shared__ float t[32][33];
    const int b = blockIdx.z;
    const int hw0 = blockIdx.x * 32, c0 = blockIdx.y * 32;
    const int tx = threadIdx.x, ty = threadIdx.y;
#pragma unroll
    for (int i = 0; i < 4; i++){
        int c = c0 + ty + i*8;
        t[ty + i*8][tx] = x[(size_t)b*C_*HW + (size_t)c*HW + hw0 + tx];
    }
    __syncthreads();
#pragma unroll
    for (int i = 0; i < 4; i++){
        int hw = hw0 + ty + i*8;
        xT[(size_t)(b*HW + hw)*256 + c0 + tx] = __float2half_rn(t[tx][ty + i*8]);
    }
}

// ---------------- convert weights to half ----------------
__global__ __launch_bounds__(256) void convw_k(
    const float* __restrict__ qkvw, const float* __restrict__ projw,
    const float* __restrict__ w1, const float* __restrict__ w2, __half* __restrict__ gw)
{
    int i = blockIdx.x * 256 + threadIdx.x;
    float v;
    if (i < 196608)      v = qkvw[i];
    else if (i < 262144) v = projw[i - 196608];
    else if (i < 393216) v = w1[i - 262144];
    else                 v = w2[i - 393216];
    gw[i] = __float2half_rn(v);
}

// ---------------- fused attention + fc-mix + LayerNorm ----------------
// Block: 256 threads = 8 warps = 8 pixels. Warp: 4 dilations x 8 lanes, 8 ch/lane.
__global__ __launch_bounds__(256) void attn_ln_k(
    const __half* __restrict__ qkv,
    const float* __restrict__ fcw, const float* __restrict__ fcb,
    const float* __restrict__ lng, const float* __restrict__ lnb,
    __half* __restrict__ y2)
{
    __shared__ float sOut[2048];      // [8 pixels][4 dil][64 ch]
    __shared__ float ssum[2][8][4], ssq[2][8][4];

    const int tid  = threadIdx.x;
    const int wid  = tid >> 5;        // pixel in block
    const int lane = tid & 31;
    const int dil  = lane >> 3;
    const int c0   = (lane & 7) * 8;
    const int pix  = blockIdx.x * 8 + wid;
    const int b    = pix / HW;
    const int pixl = pix - b * HW;
    const int y    = pixl / Ww;
    const int x    = pixl - y * Ww;
    const int r    = 1 << dil;

    const __half* base = qkv + (size_t)b * HW * 768 + dil*64 + c0;

    int offs[9]; unsigned vm = 0;
#pragma unroll
    for (int j = 0; j < 9; j++){
        const int yy = y + (j/3 - 1) * r;
        const int xx = x + (j%3 - 1) * r;
        offs[j] = (yy*Ww + xx) * 768;
        if ((unsigned)yy < (unsigned)Hh && (unsigned)xx < (unsigned)Ww) vm |= 1u << j;
    }

    uint4 qu = *(const uint4*)(base + (size_t)pixl*768);
    const __half2 qh0 = *(__half2*)&qu.x;
    const __half2 qh1 = *(__half2*)&qu.y;
    const __half2 qh2 = *(__half2*)&qu.z;
    const __half2 qh3 = *(__half2*)&qu.w;

    float sc[9];
#pragma unroll
    for (int j = 0; j < 9; j++){
        float s = 0.f;
        if (vm & (1u << j)){
            uint4 ku = *(const uint4*)(base + offs[j] + 256);
            __half2 a0 = __hmul2(qh0, *(__half2*)&ku.x);
            a0 = __hfma2(qh1, *(__half2*)&ku.y, a0);
            __half2 a1 = __hmul2(qh2, *(__half2*)&ku.z);
            a1 = __hfma2(qh3, *(__half2*)&ku.w, a1);
            s = __low2float(a0) + __high2float(a0) + __low2float(a1) + __high2float(a1);
        }
#pragma unroll
        for (int o = 4; o > 0; o >>= 1) s += __shfl_xor_sync(0xffffffffu, s, o);
        sc[j] = s * 0.125f;
    }

    float mx = sc[0];
#pragma unroll
    for (int j = 1; j < 9; j++) mx = fmaxf(mx, sc[j]);
    float p[9], sum = 0.f;
#pragma unroll
    for (int j = 0; j < 9; j++){ p[j] = __expf(sc[j] - mx); sum += p[j]; }
    const float inv = __frcp_rn(sum);

    float a[8];
#pragma unroll
    for (int e = 0; e < 8; e++) a[e] = 0.f;
#pragma unroll
    for (int j = 0; j < 9; j++){
        if (vm & (1u << j)){
            uint4 vu = *(const uint4*)(base + offs[j] + 512);
            const float2 v0 = __half22float2(*(__half2*)&vu.x);
            const float2 v1 = __half22float2(*(__half2*)&vu.y);
            const float2 v2 = __half22float2(*(__half2*)&vu.z);
            const float2 v3 = __half22float2(*(__half2*)&vu.w);
            a[0] += p[j]*v0.x; a[1] += p[j]*v0.y;
            a[2] += p[j]*v1.x; a[3] += p[j]*v1.y;
            a[4] += p[j]*v2.x; a[5] += p[j]*v2.y;
            a[6] += p[j]*v3.x; a[7] += p[j]*v3.y;
        }
    }
    float* so = sOut + wid*256 + dil*64 + c0;
    *(float4*)(so)     = make_float4(a[0]*inv, a[1]*inv, a[2]*inv, a[3]*inv);
    *(float4*)(so + 4) = make_float4(a[4]*inv, a[5]*inv, a[6]*inv, a[7]*inv);
    __syncthreads();

    // fc mix + residual + LN(64): 2 passes of 4 pixels; thread = (px, channel)
    const int pxl_ = tid >> 6;        // 0..3
    const int c    = tid & 63;
    float fv[2][4];
#pragma unroll
    for (int it = 0; it < 2; it++){
        const int px = pxl_ + it*4;
        const float* sp = sOut + px*256;
        const float s0 = sp[c], s1 = sp[64 + c], s2 = sp[128 + c], s3 = sp[192 + c];
        const float sv[4] = {s0, s1, s2, s3};
        float sm[4], sq[4];
#pragma unroll
        for (int t = 0; t < 4; t++){
            fv[it][t] = fcw[t*4+0]*s0 + fcw[t*4+1]*s1 + fcw[t*4+2]*s2 + fcw[t*4+3]*s3
                        + fcb[t] + sv[t];
            sm[t] = fv[it][t]; sq[t] = fv[it][t]*fv[it][t];
        }
#pragma unroll
        for (int o = 16; o > 0; o >>= 1){
#pragma unroll
            for (int t = 0; t < 4; t++){
                sm[t] += __shfl_xor_sync(0xffffffffu, sm[t], o);
                sq[t] += __shfl_xor_sync(0xffffffffu, sq[t], o);
            }
        }
        if (lane == 0){
#pragma unroll
            for (int t = 0; t < 4; t++){ ssum[it][wid][t] = sm[t]; ssq[it][wid][t] = sq[t]; }
        }
    }
    __syncthreads();
    const float lg = lng[c], lb = lnb[c];
#pragma unroll
    for (int it = 0; it < 2; it++){
        const int px = pxl_ + it*4;
        __half* yo = y2 + (size_t)(blockIdx.x*8 + px)*256 + c;
#pragma unroll
        for (int t = 0; t < 4; t++){
            const float tot  = ssum[it][pxl_*2][t] + ssum[it][pxl_*2+1][t];
            const float totq = ssq[it][pxl_*2][t]  + ssq[it][pxl_*2+1][t];
            const float mu  = tot * (1.f/64.f);
            const float var = totq * (1.f/64.f) - mu*mu;
            yo[t*64] = __float2half_rn((fv[it][t] - mu) * rsqrtf(var + EPSF) * lg + lb);
        }
    }
}

// ---------------- launch ----------------
extern "C" void kernel_launch(void* const* d_in, const int* in_sizes, int n_in,
                              void* d_out, int out_size)
{
    const float* x      = (const float*)d_in[0];
    const float* qkv_w  = (const float*)d_in[1];
    const float* qkv_b  = (const float*)d_in[2];
    const float* fc_w   = (const float*)d_in[3];
    const float* fc_b   = (const float*)d_in[4];
    const float* ln_g   = (const float*)d_in[5];
    const float* ln_b   = (const float*)d_in[6];
    const float* proj_w = (const float*)d_in[7];
    const float* proj_b = (const float*)d_in[8];
    const float* w1     = (const float*)d_in[9];
    const float* bn1_g  = (const float*)d_in[10];
    const float* bn1_b  = (const float*)d_in[11];
    const float* bn1_m  = (const float*)d_in[12];
    const float* bn1_v  = (const float*)d_in[13];
    const float* w2     = (const float*)d_in[14];
    const float* bn2_g  = (const float*)d_in[15];
    const float* bn2_b  = (const float*)d_in[16];
    const float* bn2_m  = (const float*)d_in[17];
    const float* bn2_v  = (const float*)d_in[18];
    float* out = (float*)d_out;

    __half *xT, *qkv, *y2, *x1h, *hb, *gw;
    float *x1f;
    cudaGetSymbolAddress((void**)&xT,  g_xT);
    cudaGetSymbolAddress((void**)&qkv, g_qkv);
    cudaGetSymbolAddress((void**)&y2,  g_y2);
    cudaGetSymbolAddress((void**)&x1h, g_x1h);
    cudaGetSymbolAddress((void**)&x1f, g_x1f);
    cudaGetSymbolAddress((void**)&hb,  g_h);
    cudaGetSymbolAddress((void**)&gw,  g_w);

    cudaFuncSetAttribute(gemm_mma<0>, cudaFuncAttributeMaxDynamicSharedMemorySize, SMEM_BYTES);
    cudaFuncSetAttribute(gemm_mma<1>, cudaFuncAttributeMaxDynamicSharedMemorySize, SMEM_BYTES);
    cudaFuncSetAttribute(gemm_mma<2>, cudaFuncAttributeMaxDynamicSharedMemorySize, SMEM_BYTES);
    cudaFuncSetAttribute(gemm_mma<3>, cudaFuncAttributeMaxDynamicSharedMemorySize, SMEM_BYTES);

    convw_k<<<2048, 256>>>(qkv_w, proj_w, w1, w2, gw);
    transpose_k<<<dim3(HW/32, C_/32, B_), dim3(32, 8)>>>(x, xT);

    // 1) qkv = xT @ qkv_w^T + b : [51200][768] half
    gemm_mma<0><<<dim3(6, 400), 256, SMEM_BYTES>>>(
        xT, gw, qkv, nullptr, 256, 768, qkv_b, nullptr, nullptr, nullptr, nullptr, nullptr);

    // 2+3) attention + fc mix + LN (fused) -> y2 half
    attn_ln_k<<<NPIX/8, 256>>>(qkv, fc_w, fc_b, ln_g, ln_b, y2);

    // 4) x1 = y2 @ proj_w^T + proj_b + x -> x1h (half) / x1f (float)
    gemm_mma<1><<<dim3(2, 400), 256, SMEM_BYTES>>>(
        y2, gw + 196608, x1h, x1f, 256, 256, proj_b, x, nullptr, nullptr, nullptr, nullptr);

    // 5) h = silu(bn1(x1 @ w1^T)) : [51200][512] half
    gemm_mma<2><<<dim3(4, 400), 256, SMEM_BYTES>>>(
        x1h, gw + 262144, hb, nullptr, 256, 512, nullptr, nullptr, bn1_g, bn1_b, bn1_m, bn1_v);

    // 6) out = x1 + bn2(h @ w2^T) -> [B][C][HW] float
    gemm_mma<3><<<dim3(2, 400), 256, SMEM_BYTES>>>(
        hb, gw + 393216, nullptr, out, 512, 256, nullptr, x1f, bn2_g, bn2_b, bn2_m, bn2_v);
}

// round 12
// speedup vs baseline: 1.2018x; 1.0672x over previous
#include <cuda_runtime.h>
#include <cuda_fp16.h>
#include <cstdint>
#include <math.h>

#define B_  8
#define C_  256
#define Hh  80
#define Ww  80
#define HW  6400
#define NPIX 51200
#define EPSF 1e-5f

#define KC 64
#define STAGES 3
#define TSTRH 72                 // smem row stride in halfs (144B): LDSM conflict-free
#define ST_B (128*TSTRH*2)       // 18432 B per operand stage
#define SMEM_BYTES (STAGES*2*ST_B)   // 110592 B per CTA

// ---------------- scratch ----------------
__device__ __half g_xT [(size_t)NPIX*256];
__device__ __half g_qkv[(size_t)NPIX*768];
__device__ __half g_y2 [(size_t)NPIX*256];
__device__ __half g_x1h[(size_t)NPIX*256];
__device__ __half g_h  [(size_t)NPIX*512];
__device__ __half g_w  [524288];

// ---------------- helpers ----------------
__device__ __forceinline__ uint32_t s2u(const void* p){
    uint32_t a; asm("{ .reg .u64 t; cvta.to.shared.u64 t, %1; cvt.u32.u64 %0, t; }" : "=r"(a) : "l"(p)); return a;
}
#define CPA16(d,s) asm volatile("cp.async.cg.shared.global [%0], [%1], 16;" :: "r"(d), "l"(s))
#define CPCOMMIT() asm volatile("cp.async.commit_group;" ::: "memory")
#define CPWAIT(n)  asm volatile("cp.async.wait_group %0;" :: "n"(n) : "memory")
#define LDSM4(r0,r1,r2,r3,a) \
    asm volatile("ldmatrix.sync.aligned.m8n8.x4.shared.b16 {%0,%1,%2,%3}, [%4];" \
        : "=r"(r0), "=r"(r1), "=r"(r2), "=r"(r3) : "r"(a))

__device__ __forceinline__ void mma16(float* d, const uint32_t* a, uint32_t b0, uint32_t b1){
    asm volatile("mma.sync.aligned.m16n8k16.row.col.f32.f16.f16.f32 "
        "{%0,%1,%2,%3}, {%4,%5,%6,%7}, {%8,%9}, {%0,%1,%2,%3};"
        : "+f"(d[0]), "+f"(d[1]), "+f"(d[2]), "+f"(d[3])
        : "r"(a[0]), "r"(a[1]), "r"(a[2]), "r"(a[3]), "r"(b0), "r"(b1));
}

// ---------------- fp16 mma.sync GEMM, 128x128 tile, 8 warps, KC=64, 3 stages ----------------
// MODE 0: Ch = acc + bias[n]                       -> qkv half (Cstride 768)
// MODE 1: Ch = half(acc+bias+resx)                 -> x1h  (resx = x[b][c][hw] fp32)
// MODE 2: Ch = half(silu(acc*sc+sh))               -> h half (Cstride 512)
// MODE 3: Cf = acc*sc+sh + res(half) -> out[b][n][pixl] (smem-staged transposed store)
template<int MODE>
__global__ __launch_bounds__(256, 2) void gemm_mma(
    const __half* __restrict__ A, const __half* __restrict__ Bw,
    __half* __restrict__ Ch, float* __restrict__ Cf, int Ktot, int Cstride,
    const float* __restrict__ bias, const void* __restrict__ resv,
    const float* __restrict__ gg, const float* __restrict__ bb,
    const float* __restrict__ mm, const float* __restrict__ vv)
{
    extern __shared__ float smemf[];
    const uint32_t smem_b = s2u(smemf);

    const int tid  = threadIdx.x;
    const int wid  = tid >> 5;
    const int lane = tid & 31;
    const int wm   = wid & 1;         // 2 warps in M (64 rows)
    const int wn   = wid >> 1;        // 4 warps in N (32 cols)
    const int lr   = lane >> 2;
    const int lc   = lane & 3;
    const int m0   = blockIdx.y * 128;
    const int n0   = blockIdx.x * 128;

    const uint32_t aoff = (uint32_t)(((wm*64 + ((lane>>3)&1)*8 + (lane&7))*TSTRH + (lane>>4)*8) * 2);
    const uint32_t boff = (uint32_t)(((wn*32 + (lane>>4)*8 + (lane&7))*TSTRH + ((lane>>3)&1)*8) * 2);

    float d[4][4][4];
#pragma unroll
    for (int i = 0; i < 4; i++)
#pragma unroll
        for (int j = 0; j < 4; j++)
#pragma unroll
            for (int e = 0; e < 4; e++) d[i][j][e] = 0.f;

    const int nch = Ktot / KC;

    auto load = [&](int cc){
        const int s = cc % STAGES;
        const __half* Ab = A + (size_t)m0 * Ktot + cc*KC;
        const uint32_t da = smem_b + (2*s)*ST_B;
#pragma unroll
        for (int t = 0; t < 4; t++){
            int i = tid + t*256;
            int r = i >> 3, c = i & 7;
            CPA16(da + r*TSTRH*2 + c*16, (const void*)(Ab + (size_t)r*Ktot + c*8));
        }
        const __half* Bb = Bw + (size_t)n0 * Ktot + cc*KC;
        const uint32_t db = smem_b + (2*s+1)*ST_B;
#pragma unroll
        for (int t = 0; t < 4; t++){
            int i = tid + t*256;
            int r = i >> 3, c = i & 7;
            CPA16(db + r*TSTRH*2 + c*16, (const void*)(Bb + (size_t)r*Ktot + c*8));
        }
        CPCOMMIT();
    };

    load(0); load(1);

    for (int cc = 0; cc < nch; cc++){
        const int rem = nch - 1 - cc;
        if (rem >= 1) CPWAIT(1);
        else          CPWAIT(0);
        __syncthreads();
        if (cc + 2 < nch) load(cc + 2);

        const int s = cc % STAGES;
        const uint32_t aBase = smem_b + (2*s)*ST_B + aoff;
        const uint32_t bBase = smem_b + (2*s+1)*ST_B + boff;
#pragma unroll
        for (int kk = 0; kk < 4; kk++){
            uint32_t a[4][4], bf[2][4];
#pragma unroll
            for (int mi = 0; mi < 4; mi++)
                LDSM4(a[mi][0], a[mi][1], a[mi][2], a[mi][3],
                      aBase + mi*(16*TSTRH*2) + kk*32);
#pragma unroll
            for (int np = 0; np < 2; np++)
                LDSM4(bf[np][0], bf[np][1], bf[np][2], bf[np][3],
                      bBase + np*(16*TSTRH*2) + kk*32);
#pragma unroll
            for (int np = 0; np < 2; np++)
#pragma unroll
                for (int mi = 0; mi < 4; mi++){
                    mma16(d[mi][2*np],   a[mi], bf[np][0], bf[np][1]);
                    mma16(d[mi][2*np+1], a[mi], bf[np][2], bf[np][3]);
                }
        }
    }

    // ---------------- epilogue ----------------
    const int lc2 = lc * 2;

    if (MODE != 3){
        const int bidx  = (MODE == 1) ? m0 / HW : 0;
        const int pixl0 = (MODE == 1) ? m0 - bidx*HW : 0;
        const float* xb = (MODE == 1) ? (const float*)resv + (size_t)bidx*C_*HW : (const float*)0;
#pragma unroll
        for (int mi = 0; mi < 4; mi++){
#pragma unroll
            for (int rr = 0; rr < 2; rr++){
                const int rl = wm*64 + mi*16 + lr + rr*8;
                const int r  = m0 + rl;
                __half* crow = Ch + (size_t)r*Cstride + n0 + wn*32;
                const int pixl = pixl0 + rl;
#pragma unroll
                for (int ni = 0; ni < 4; ni++){
                    const int c = ni*8 + lc2;
                    const int gc = n0 + wn*32 + c;
                    float v0 = d[mi][ni][rr*2+0];
                    float v1 = d[mi][ni][rr*2+1];
                    if (MODE == 0){
                        v0 += bias[gc]; v1 += bias[gc+1];
                        *(__half2*)(crow + c) = __floats2half2_rn(v0, v1);
                    } else if (MODE == 1){
                        v0 += bias[gc]   + xb[(size_t)gc*HW + pixl];
                        v1 += bias[gc+1] + xb[(size_t)(gc+1)*HW + pixl];
                        *(__half2*)(crow + c) = __floats2half2_rn(v0, v1);
                    } else { // MODE 2
                        float i0 = gg[gc]   * rsqrtf(vv[gc]   + EPSF);
                        float i1 = gg[gc+1] * rsqrtf(vv[gc+1] + EPSF);
                        v0 = v0*i0 + (bb[gc]   - mm[gc]  *i0);
                        v1 = v1*i1 + (bb[gc+1] - mm[gc+1]*i1);
                        v0 = v0 * __frcp_rn(1.f + __expf(-v0));
                        v1 = v1 * __frcp_rn(1.f + __expf(-v1));
                        *(__half2*)(crow + c) = __floats2half2_rn(v0, v1);
                    }
                }
            }
        }
    } else {
        // MODE 3: bn2 + residual (half x1), smem-transposed coalesced store to [b][c][hw]
        const __half* resh = (const __half*)resv;
        __syncthreads();
        float* stg = smemf + wid * (64*33);
#pragma unroll
        for (int ni = 0; ni < 4; ni++){
            const int gc = n0 + wn*32 + ni*8 + lc2;
            const float i0 = gg[gc]   * rsqrtf(vv[gc]   + EPSF);
            const float i1 = gg[gc+1] * rsqrtf(vv[gc+1] + EPSF);
            const float s0 = bb[gc]   - mm[gc]  *i0;
            const float s1 = bb[gc+1] - mm[gc+1]*i1;
#pragma unroll
            for (int mi = 0; mi < 4; mi++){
#pragma unroll
                for (int rr = 0; rr < 2; rr++){
                    const int lrow = mi*16 + lr + rr*8;
                    const int grow = m0 + wm*64 + lrow;
                    const float2 rf = __half22float2(*(const __half2*)(resh + (size_t)grow*256 + gc));
                    stg[lrow*33 + ni*8 + lc2]     = d[mi][ni][rr*2+0]*i0 + s0 + rf.x;
                    stg[lrow*33 + ni*8 + lc2 + 1] = d[mi][ni][rr*2+1]*i1 + s1 + rf.y;
                }
            }
        }
        __syncwarp();
        const int pix0 = m0 + wm*64;
        const int bidx = pix0 / HW;
        const int pixl = pix0 - bidx*HW;
        float* ob = Cf + (size_t)bidx*C_*HW + pixl;
#pragma unroll
        for (int n = 0; n < 32; n++){
            const int gc = n0 + wn*32 + n;
            ob[(size_t)gc*HW + lane]      = stg[lane*33 + n];
            ob[(size_t)gc*HW + lane + 32] = stg[(lane+32)*33 + n];
        }
    }
}

// ---------------- transpose x [B][C][HW] -> xT half (vectorized) ----------------
// blockDim (8,32): load float4 rows, store half4 (uint2) rows.
__global__ __launch_bounds__(256) void transpose_k(const float* __restrict__ x,
                                                   __half* __restrict__ xT)
{
    __shared__ float t[32][33];
    const int b = blockIdx.z;
    const int hw0 = blockIdx.x * 32, c0 = blockIdx.y * 32;
    const int tx = threadIdx.x;   // 0..7
    const int ty = threadIdx.y;   // 0..31

    const float4 v = *(const float4*)(x + (size_t)b*C_*HW + (size_t)(c0+ty)*HW + hw0 + tx*4);
    t[ty][tx*4+0] = v.x; t[ty][tx*4+1] = v.y; t[ty][tx*4+2] = v.z; t[ty][tx*4+3] = v.w;
    __syncthreads();

    const float f0 = t[tx*4+0][ty], f1 = t[tx*4+1][ty];
    const float f2 = t[tx*4+2][ty], f3 = t[tx*4+3][ty];
    uint2 o;
    __half2 h01 = __floats2half2_rn(f0, f1);
    __half2 h23 = __floats2half2_rn(f2, f3);
    o.x = *(uint32_t*)&h01; o.y = *(uint32_t*)&h23;
    *(uint2*)(xT + (size_t)(b*HW + hw0 + ty)*256 + c0 + tx*4) = o;
}

// ---------------- convert weights to half ----------------
__global__ __launch_bounds__(256) void convw_k(
    const float* __restrict__ qkvw, const float* __restrict__ projw,
    const float* __restrict__ w1, const float* __restrict__ w2, __half* __restrict__ gw)
{
    int i = blockIdx.x * 256 + threadIdx.x;
    float v;
    if (i < 196608)      v = qkvw[i];
    else if (i < 262144) v = projw[i - 196608];
    else if (i < 393216) v = w1[i - 262144];
    else                 v = w2[i - 393216];
    gw[i] = __float2half_rn(v);
}

// ---------------- fused attention + fc-mix + LayerNorm ----------------
// Block: 256 threads = 8 warps = 8 pixels. Warp: 4 dilations x 8 lanes, 8 ch/lane.
__global__ __launch_bounds__(256) void attn_ln_k(
    const __half* __restrict__ qkv,
    const float* __restrict__ fcw, const float* __restrict__ fcb,
    const float* __restrict__ lng, const float* __restrict__ lnb,
    __half* __restrict__ y2)
{
    __shared__ float sOut[2048];      // [8 pixels][4 dil][64 ch]
    __shared__ float ssum[2][8][4], ssq[2][8][4];

    const int tid  = threadIdx.x;
    const int wid  = tid >> 5;        // pixel in block
    const int lane = tid & 31;
    const int dil  = lane >> 3;
    const int c0   = (lane & 7) * 8;
    const int pix  = blockIdx.x * 8 + wid;
    const int b    = pix / HW;
    const int pixl = pix - b * HW;
    const int y    = pixl / Ww;
    const int x    = pixl - y * Ww;
    const int r    = 1 << dil;

    const __half* base = qkv + (size_t)b * HW * 768 + dil*64 + c0;

    int offs[9]; unsigned vm = 0;
#pragma unroll
    for (int j = 0; j < 9; j++){
        const int yy = y + (j/3 - 1) * r;
        const int xx = x + (j%3 - 1) * r;
        offs[j] = (yy*Ww + xx) * 768;
        if ((unsigned)yy < (unsigned)Hh && (unsigned)xx < (unsigned)Ww) vm |= 1u << j;
    }

    uint4 qu = *(const uint4*)(base + (size_t)pixl*768);
    const __half2 qh0 = *(__half2*)&qu.x;
    const __half2 qh1 = *(__half2*)&qu.y;
    const __half2 qh2 = *(__half2*)&qu.z;
    const __half2 qh3 = *(__half2*)&qu.w;

    float sc[9];
#pragma unroll
    for (int j = 0; j < 9; j++){
        float s = 0.f;
        if (vm & (1u << j)){
            uint4 ku = *(const uint4*)(base + offs[j] + 256);
            __half2 a0 = __hmul2(qh0, *(__half2*)&ku.x);
            a0 = __hfma2(qh1, *(__half2*)&ku.y, a0);
            __half2 a1 = __hmul2(qh2, *(__half2*)&ku.z);
            a1 = __hfma2(qh3, *(__half2*)&ku.w, a1);
            s = __low2float(a0) + __high2float(a0) + __low2float(a1) + __high2float(a1);
        }
#pragma unroll
        for (int o = 4; o > 0; o >>= 1) s += __shfl_xor_sync(0xffffffffu, s, o);
        sc[j] = s * 0.125f;
    }

    float mx = sc[0];
#pragma unroll
    for (int j = 1; j < 9; j++) mx = fmaxf(mx, sc[j]);
    float p[9], sum = 0.f;
#pragma unroll
    for (int j = 0; j < 9; j++){ p[j] = __expf(sc[j] - mx); sum += p[j]; }
    const float inv = __frcp_rn(sum);

    float a[8];
#pragma unroll
    for (int e = 0; e < 8; e++) a[e] = 0.f;
#pragma unroll
    for (int j = 0; j < 9; j++){
        if (vm & (1u << j)){
            uint4 vu = *(const uint4*)(base + offs[j] + 512);
            const float2 v0 = __half22float2(*(__half2*)&vu.x);
            const float2 v1 = __half22float2(*(__half2*)&vu.y);
            const float2 v2 = __half22float2(*(__half2*)&vu.z);
            const float2 v3 = __half22float2(*(__half2*)&vu.w);
            a[0] += p[j]*v0.x; a[1] += p[j]*v0.y;
            a[2] += p[j]*v1.x; a[3] += p[j]*v1.y;
            a[4] += p[j]*v2.x; a[5] += p[j]*v2.y;
            a[6] += p[j]*v3.x; a[7] += p[j]*v3.y;
        }
    }
    float* so = sOut + wid*256 + dil*64 + c0;
    *(float4*)(so)     = make_float4(a[0]*inv, a[1]*inv, a[2]*inv, a[3]*inv);
    *(float4*)(so + 4) = make_float4(a[4]*inv, a[5]*inv, a[6]*inv, a[7]*inv);
    __syncthreads();

    // fc mix + residual + LN(64): 2 passes of 4 pixels; thread = (px, channel)
    const int pxl_ = tid >> 6;        // 0..3
    const int c    = tid & 63;
    float fv[2][4];
#pragma unroll
    for (int it = 0; it < 2; it++){
        const int px = pxl_ + it*4;
        const float* sp = sOut + px*256;
        const float s0 = sp[c], s1 = sp[64 + c], s2 = sp[128 + c], s3 = sp[192 + c];
        const float sv[4] = {s0, s1, s2, s3};
        float sm[4], sq[4];
#pragma unroll
        for (int t = 0; t < 4; t++){
            fv[it][t] = fcw[t*4+0]*s0 + fcw[t*4+1]*s1 + fcw[t*4+2]*s2 + fcw[t*4+3]*s3
                        + fcb[t] + sv[t];
            sm[t] = fv[it][t]; sq[t] = fv[it][t]*fv[it][t];
        }
#pragma unroll
        for (int o = 16; o > 0; o >>= 1){
#pragma unroll
            for (int t = 0; t < 4; t++){
                sm[t] += __shfl_xor_sync(0xffffffffu, sm[t], o);
                sq[t] += __shfl_xor_sync(0xffffffffu, sq[t], o);
            }
        }
        if (lane == 0){
#pragma unroll
            for (int t = 0; t < 4; t++){ ssum[it][wid][t] = sm[t]; ssq[it][wid][t] = sq[t]; }
        }
    }
    __syncthreads();
    const float lg = lng[c], lb = lnb[c];
#pragma unroll
    for (int it = 0; it < 2; it++){
        const int px = pxl_ + it*4;
        __half* yo = y2 + (size_t)(blockIdx.x*8 + px)*256 + c;
#pragma unroll
        for (int t = 0; t < 4; t++){
            const float tot  = ssum[it][pxl_*2][t] + ssum[it][pxl_*2+1][t];
            const float totq = ssq[it][pxl_*2][t]  + ssq[it][pxl_*2+1][t];
            const float mu  = tot * (1.f/64.f);
            const float var = totq * (1.f/64.f) - mu*mu;
            yo[t*64] = __float2half_rn((fv[it][t] - mu) * rsqrtf(var + EPSF) * lg + lb);
        }
    }
}

// ---------------- launch ----------------
extern "C" void kernel_launch(void* const* d_in, const int* in_sizes, int n_in,
                              void* d_out, int out_size)
{
    const float* x      = (const float*)d_in[0];
    const float* qkv_w  = (const float*)d_in[1];
    const float* qkv_b  = (const float*)d_in[2];
    const float* fc_w   = (const float*)d_in[3];
    const float* fc_b   = (const float*)d_in[4];
    const float* ln_g   = (const float*)d_in[5];
    const float* ln_b   = (const float*)d_in[6];
    const float* proj_w = (const float*)d_in[7];
    const float* proj_b = (const float*)d_in[8];
    const float* w1     = (const float*)d_in[9];
    const float* bn1_g  = (const float*)d_in[10];
    const float* bn1_b  = (const float*)d_in[11];
    const float* bn1_m  = (const float*)d_in[12];
    const float* bn1_v  = (const float*)d_in[13];
    const float* w2     = (const float*)d_in[14];
    const float* bn2_g  = (const float*)d_in[15];
    const float* bn2_b  = (const float*)d_in[16];
    const float* bn2_m  = (const float*)d_in[17];
    const float* bn2_v  = (const float*)d_in[18];
    float* out = (float*)d_out;

    __half *xT, *qkv, *y2, *x1h, *hb, *gw;
    cudaGetSymbolAddress((void**)&xT,  g_xT);
    cudaGetSymbolAddress((void**)&qkv, g_qkv);
    cudaGetSymbolAddress((void**)&y2,  g_y2);
    cudaGetSymbolAddress((void**)&x1h, g_x1h);
    cudaGetSymbolAddress((void**)&hb,  g_h);
    cudaGetSymbolAddress((void**)&gw,  g_w);

    cudaFuncSetAttribute(gemm_mma<0>, cudaFuncAttributeMaxDynamicSharedMemorySize, SMEM_BYTES);
    cudaFuncSetAttribute(gemm_mma<1>, cudaFuncAttributeMaxDynamicSharedMemorySize, SMEM_BYTES);
    cudaFuncSetAttribute(gemm_mma<2>, cudaFuncAttributeMaxDynamicSharedMemorySize, SMEM_BYTES);
    cudaFuncSetAttribute(gemm_mma<3>, cudaFuncAttributeMaxDynamicSharedMemorySize, SMEM_BYTES);

    convw_k<<<2048, 256>>>(qkv_w, proj_w, w1, w2, gw);
    transpose_k<<<dim3(HW/32, C_/32, B_), dim3(8, 32)>>>(x, xT);

    // 1) qkv = xT @ qkv_w^T + b : [51200][768] half
    gemm_mma<0><<<dim3(6, 400), 256, SMEM_BYTES>>>(
        xT, gw, qkv, nullptr, 256, 768, qkv_b, nullptr, nullptr, nullptr, nullptr, nullptr);

    // 2+3) attention + fc mix + LN (fused) -> y2 half
    attn_ln_k<<<NPIX/8, 256>>>(qkv, fc_w, fc_b, ln_g, ln_b, y2);

    // 4) x1 = y2 @ proj_w^T + proj_b + x -> x1h (half only)
    gemm_mma<1><<<dim3(2, 400), 256, SMEM_BYTES>>>(
        y2, gw + 196608, x1h, nullptr, 256, 256, proj_b, x, nullptr, nullptr, nullptr, nullptr);

    // 5) h = silu(bn1(x1 @ w1^T)) : [51200][512] half
    gemm_mma<2><<<dim3(4, 400), 256, SMEM_BYTES>>>(
        x1h, gw + 262144, hb, nullptr, 256, 512, nullptr, nullptr, bn1_g, bn1_b, bn1_m, bn1_v);

    // 6) out = x1(half) + bn2(h @ w2^T) -> [B][C][HW] float
    gemm_mma<3><<<dim3(2, 400), 256, SMEM_BYTES>>>(
        hb, gw + 393216, nullptr, out, 512, 256, nullptr, x1h, bn2_g, bn2_b, bn2_m, bn2_v);
}

// round 13
// speedup vs baseline: 1.2348x; 1.0275x over previous
#include <cuda_runtime.h>
#include <cuda_fp16.h>
#include <cstdint>
#include <math.h>

#define B_  8
#define C_  256
#define Hh  80
#define Ww  80
#define HW  6400
#define NPIX 51200
#define EPSF 1e-5f

#define KC 64
#define STAGES 3
#define TSTRH 72                 // smem row stride in halfs (144B): LDSM conflict-free
#define ST_B (128*TSTRH*2)       // 18432 B per operand stage
#define SMEM_BYTES (STAGES*2*ST_B)   // 110592 B per CTA

// ---------------- scratch ----------------
__device__ __half g_xT [(size_t)NPIX*256];
__device__ __half g_qkv[(size_t)NPIX*768];
__device__ __half g_y2 [(size_t)NPIX*256];
__device__ __half g_x1h[(size_t)NPIX*256];
__device__ __half g_h  [(size_t)NPIX*512];
__device__ __half g_w  [524288];

// ---------------- helpers ----------------
__device__ __forceinline__ uint32_t s2u(const void* p){
    uint32_t a; asm("{ .reg .u64 t; cvta.to.shared.u64 t, %1; cvt.u32.u64 %0, t; }" : "=r"(a) : "l"(p)); return a;
}
#define CPA16(d,s) asm volatile("cp.async.cg.shared.global [%0], [%1], 16;" :: "r"(d), "l"(s))
#define CPCOMMIT() asm volatile("cp.async.commit_group;" ::: "memory")
#define CPWAIT(n)  asm volatile("cp.async.wait_group %0;" :: "n"(n) : "memory")
#define LDSM4(r0,r1,r2,r3,a) \
    asm volatile("ldmatrix.sync.aligned.m8n8.x4.shared.b16 {%0,%1,%2,%3}, [%4];" \
        : "=r"(r0), "=r"(r1), "=r"(r2), "=r"(r3) : "r"(a))

__device__ __forceinline__ void mma16(float* d, const uint32_t* a, uint32_t b0, uint32_t b1){
    asm volatile("mma.sync.aligned.m16n8k16.row.col.f32.f16.f16.f32 "
        "{%0,%1,%2,%3}, {%4,%5,%6,%7}, {%8,%9}, {%0,%1,%2,%3};"
        : "+f"(d[0]), "+f"(d[1]), "+f"(d[2]), "+f"(d[3])
        : "r"(a[0]), "r"(a[1]), "r"(a[2]), "r"(a[3]), "r"(b0), "r"(b1));
}

// ---------------- fp16 mma.sync GEMM, 128x128 tile, 8 warps, KC=64, 3 stages ----------------
// MODE 0: Ch = acc + bias[n]                       -> qkv half (Cstride 768)
// MODE 1: Ch = half(acc+bias+res(half [pix][c]))   -> x1h
// MODE 2: Ch = half(silu(acc*sc+sh))               -> h half (Cstride 512)
// MODE 3: Cf = acc*sc+sh + res(half) -> out[b][n][pixl] (smem-staged transposed store)
template<int MODE>
__global__ __launch_bounds__(256, 2) void gemm_mma(
    const __half* __restrict__ A, const __half* __restrict__ Bw,
    __half* __restrict__ Ch, float* __restrict__ Cf, int Ktot, int Cstride,
    const float* __restrict__ bias, const __half* __restrict__ resh,
    const float* __restrict__ gg, const float* __restrict__ bb,
    const float* __restrict__ mm, const float* __restrict__ vv)
{
    extern __shared__ float smemf[];
    const uint32_t smem_b = s2u(smemf);

    const int tid  = threadIdx.x;
    const int wid  = tid >> 5;
    const int lane = tid & 31;
    const int wm   = wid & 1;         // 2 warps in M (64 rows)
    const int wn   = wid >> 1;        // 4 warps in N (32 cols)
    const int lr   = lane >> 2;
    const int lc   = lane & 3;
    const int m0   = blockIdx.y * 128;
    const int n0   = blockIdx.x * 128;

    const uint32_t aoff = (uint32_t)(((wm*64 + ((lane>>3)&1)*8 + (lane&7))*TSTRH + (lane>>4)*8) * 2);
    const uint32_t boff = (uint32_t)(((wn*32 + (lane>>4)*8 + (lane&7))*TSTRH + ((lane>>3)&1)*8) * 2);

    float d[4][4][4];
#pragma unroll
    for (int i = 0; i < 4; i++)
#pragma unroll
        for (int j = 0; j < 4; j++)
#pragma unroll
            for (int e = 0; e < 4; e++) d[i][j][e] = 0.f;

    const int nch = Ktot / KC;

    auto load = [&](int cc){
        const int s = cc % STAGES;
        const __half* Ab = A + (size_t)m0 * Ktot + cc*KC;
        const uint32_t da = smem_b + (2*s)*ST_B;
#pragma unroll
        for (int t = 0; t < 4; t++){
            int i = tid + t*256;
            int r = i >> 3, c = i & 7;
            CPA16(da + r*TSTRH*2 + c*16, (const void*)(Ab + (size_t)r*Ktot + c*8));
        }
        const __half* Bb = Bw + (size_t)n0 * Ktot + cc*KC;
        const uint32_t db = smem_b + (2*s+1)*ST_B;
#pragma unroll
        for (int t = 0; t < 4; t++){
            int i = tid + t*256;
            int r = i >> 3, c = i & 7;
            CPA16(db + r*TSTRH*2 + c*16, (const void*)(Bb + (size_t)r*Ktot + c*8));
        }
        CPCOMMIT();
    };

    load(0); load(1);

    for (int cc = 0; cc < nch; cc++){
        const int rem = nch - 1 - cc;
        if (rem >= 1) CPWAIT(1);
        else          CPWAIT(0);
        __syncthreads();
        if (cc + 2 < nch) load(cc + 2);

        const int s = cc % STAGES;
        const uint32_t aBase = smem_b + (2*s)*ST_B + aoff;
        const uint32_t bBase = smem_b + (2*s+1)*ST_B + boff;
#pragma unroll
        for (int kk = 0; kk < 4; kk++){
            uint32_t a[4][4], bf[2][4];
#pragma unroll
            for (int mi = 0; mi < 4; mi++)
                LDSM4(a[mi][0], a[mi][1], a[mi][2], a[mi][3],
                      aBase + mi*(16*TSTRH*2) + kk*32);
#pragma unroll
            for (int np = 0; np < 2; np++)
                LDSM4(bf[np][0], bf[np][1], bf[np][2], bf[np][3],
                      bBase + np*(16*TSTRH*2) + kk*32);
#pragma unroll
            for (int np = 0; np < 2; np++)
#pragma unroll
                for (int mi = 0; mi < 4; mi++){
                    mma16(d[mi][2*np],   a[mi], bf[np][0], bf[np][1]);
                    mma16(d[mi][2*np+1], a[mi], bf[np][2], bf[np][3]);
                }
        }
    }

    // ---------------- epilogue ----------------
    const int lc2 = lc * 2;

    if (MODE != 3){
#pragma unroll
        for (int mi = 0; mi < 4; mi++){
#pragma unroll
            for (int rr = 0; rr < 2; rr++){
                const int rl = wm*64 + mi*16 + lr + rr*8;
                const int r  = m0 + rl;
                __half* crow = Ch + (size_t)r*Cstride + n0 + wn*32;
                const __half* rrow = (MODE == 1) ? resh + (size_t)r*256 + n0 + wn*32 : (const __half*)0;
#pragma unroll
                for (int ni = 0; ni < 4; ni++){
                    const int c = ni*8 + lc2;
                    const int gc = n0 + wn*32 + c;
                    float v0 = d[mi][ni][rr*2+0];
                    float v1 = d[mi][ni][rr*2+1];
                    if (MODE == 0){
                        v0 += bias[gc]; v1 += bias[gc+1];
                        *(__half2*)(crow + c) = __floats2half2_rn(v0, v1);
                    } else if (MODE == 1){
                        const float2 rf = __half22float2(*(const __half2*)(rrow + c));
                        v0 += bias[gc]   + rf.x;
                        v1 += bias[gc+1] + rf.y;
                        *(__half2*)(crow + c) = __floats2half2_rn(v0, v1);
                    } else { // MODE 2
                        float i0 = gg[gc]   * rsqrtf(vv[gc]   + EPSF);
                        float i1 = gg[gc+1] * rsqrtf(vv[gc+1] + EPSF);
                        v0 = v0*i0 + (bb[gc]   - mm[gc]  *i0);
                        v1 = v1*i1 + (bb[gc+1] - mm[gc+1]*i1);
                        v0 = v0 * __frcp_rn(1.f + __expf(-v0));
                        v1 = v1 * __frcp_rn(1.f + __expf(-v1));
                        *(__half2*)(crow + c) = __floats2half2_rn(v0, v1);
                    }
                }
            }
        }
    } else {
        // MODE 3: bn2 + residual (half x1), smem-transposed coalesced store to [b][c][hw]
        __syncthreads();
        float* stg = smemf + wid * (64*33);
#pragma unroll
        for (int ni = 0; ni < 4; ni++){
            const int gc = n0 + wn*32 + ni*8 + lc2;
            const float i0 = gg[gc]   * rsqrtf(vv[gc]   + EPSF);
            const float i1 = gg[gc+1] * rsqrtf(vv[gc+1] + EPSF);
            const float s0 = bb[gc]   - mm[gc]  *i0;
            const float s1 = bb[gc+1] - mm[gc+1]*i1;
#pragma unroll
            for (int mi = 0; mi < 4; mi++){
#pragma unroll
                for (int rr = 0; rr < 2; rr++){
                    const int lrow = mi*16 + lr + rr*8;
                    const int grow = m0 + wm*64 + lrow;
                    const float2 rf = __half22float2(*(const __half2*)(resh + (size_t)grow*256 + gc));
                    stg[lrow*33 + ni*8 + lc2]     = d[mi][ni][rr*2+0]*i0 + s0 + rf.x;
                    stg[lrow*33 + ni*8 + lc2 + 1] = d[mi][ni][rr*2+1]*i1 + s1 + rf.y;
                }
            }
        }
        __syncwarp();
        const int pix0 = m0 + wm*64;
        const int bidx = pix0 / HW;
        const int pixl = pix0 - bidx*HW;
        float* ob = Cf + (size_t)bidx*C_*HW + pixl;
#pragma unroll
        for (int n = 0; n < 32; n++){
            const int gc = n0 + wn*32 + n;
            ob[(size_t)gc*HW + lane]      = stg[lane*33 + n];
            ob[(size_t)gc*HW + lane + 32] = stg[(lane+32)*33 + n];
        }
    }
}

// ---------------- transpose x [B][C][HW] -> xT half (vectorized) ----------------
__global__ __launch_bounds__(256) void transpose_k(const float* __restrict__ x,
                                                   __half* __restrict__ xT)
{
    __shared__ float t[32][33];
    const int b = blockIdx.z;
    const int hw0 = blockIdx.x * 32, c0 = blockIdx.y * 32;
    const int tx = threadIdx.x;   // 0..7
    const int ty = threadIdx.y;   // 0..31

    const float4 v = *(const float4*)(x + (size_t)b*C_*HW + (size_t)(c0+ty)*HW + hw0 + tx*4);
    t[ty][tx*4+0] = v.x; t[ty][tx*4+1] = v.y; t[ty][tx*4+2] = v.z; t[ty][tx*4+3] = v.w;
    __syncthreads();

    const float f0 = t[tx*4+0][ty], f1 = t[tx*4+1][ty];
    const float f2 = t[tx*4+2][ty], f3 = t[tx*4+3][ty];
    uint2 o;
    __half2 h01 = __floats2half2_rn(f0, f1);
    __half2 h23 = __floats2half2_rn(f2, f3);
    o.x = *(uint32_t*)&h01; o.y = *(uint32_t*)&h23;
    *(uint2*)(xT + (size_t)(b*HW + hw0 + ty)*256 + c0 + tx*4) = o;
}

// ---------------- convert weights to half (vectorized) ----------------
__global__ __launch_bounds__(256) void convw_k(
    const float* __restrict__ qkvw, const float* __restrict__ projw,
    const float* __restrict__ w1, const float* __restrict__ w2, __half* __restrict__ gw)
{
    int i4 = blockIdx.x * 256 + threadIdx.x;    // float4 index; 131072 total
    int i = i4 * 4;
    const float* src;
    if (i < 196608)      src = qkvw + i;
    else if (i < 262144) src = projw + (i - 196608);
    else if (i < 393216) src = w1 + (i - 262144);
    else                 src = w2 + (i - 393216);
    const float4 v = *(const float4*)src;
    __half2 h01 = __floats2half2_rn(v.x, v.y);
    __half2 h23 = __floats2half2_rn(v.z, v.w);
    uint2 o; o.x = *(uint32_t*)&h01; o.y = *(uint32_t*)&h23;
    *(uint2*)(gw + i) = o;
}

// ---------------- fused attention + fc-mix + LayerNorm ----------------
// Block: 256 threads = 8 warps = 8 pixels. Warp: 4 dilations x 8 lanes, 8 ch/lane.
__global__ __launch_bounds__(256, 5) void attn_ln_k(
    const __half* __restrict__ qkv,
    const float* __restrict__ fcw, const float* __restrict__ fcb,
    const float* __restrict__ lng, const float* __restrict__ lnb,
    __half* __restrict__ y2)
{
    __shared__ float sOut[2048];      // [8 pixels][4 dil][64 ch]
    __shared__ float ssum[2][8][4], ssq[2][8][4];

    const int tid  = threadIdx.x;
    const int wid  = tid >> 5;        // pixel in block
    const int lane = tid & 31;
    const int dil  = lane >> 3;
    const int c0   = (lane & 7) * 8;
    const int pix  = blockIdx.x * 8 + wid;
    const int b    = pix / HW;
    const int pixl = pix - b * HW;
    const int y    = pixl / Ww;
    const int x    = pixl - y * Ww;
    const int r    = 1 << dil;

    const __half* base = qkv + (size_t)b * HW * 768 + dil*64 + c0;

    int offs[9]; unsigned vm = 0;
#pragma unroll
    for (int j = 0; j < 9; j++){
        const int yy = y + (j/3 - 1) * r;
        const int xx = x + (j%3 - 1) * r;
        offs[j] = (yy*Ww + xx) * 768;
        if ((unsigned)yy < (unsigned)Hh && (unsigned)xx < (unsigned)Ww) vm |= 1u << j;
    }

    uint4 qu = *(const uint4*)(base + (size_t)pixl*768);
    const __half2 qh0 = *(__half2*)&qu.x;
    const __half2 qh1 = *(__half2*)&qu.y;
    const __half2 qh2 = *(__half2*)&qu.z;
    const __half2 qh3 = *(__half2*)&qu.w;

    float sc[9];
#pragma unroll
    for (int j = 0; j < 9; j++){
        float s = 0.f;
        if (vm & (1u << j)){
            uint4 ku = *(const uint4*)(base + offs[j] + 256);
            __half2 a0 = __hmul2(qh0, *(__half2*)&ku.x);
            a0 = __hfma2(qh1, *(__half2*)&ku.y, a0);
            __half2 a1 = __hmul2(qh2, *(__half2*)&ku.z);
            a1 = __hfma2(qh3, *(__half2*)&ku.w, a1);
            s = __low2float(a0) + __high2float(a0) + __low2float(a1) + __high2float(a1);
        }
#pragma unroll
        for (int o = 4; o > 0; o >>= 1) s += __shfl_xor_sync(0xffffffffu, s, o);
        sc[j] = s * 0.125f;
    }

    float mx = sc[0];
#pragma unroll
    for (int j = 1; j < 9; j++) mx = fmaxf(mx, sc[j]);
    float p[9], sum = 0.f;
#pragma unroll
    for (int j = 0; j < 9; j++){ p[j] = __expf(sc[j] - mx); sum += p[j]; }
    const float inv = __frcp_rn(sum);

    float a[8];
#pragma unroll
    for (int e = 0; e < 8; e++) a[e] = 0.f;
#pragma unroll
    for (int j = 0; j < 9; j++){
        if (vm & (1u << j)){
            uint4 vu = *(const uint4*)(base + offs[j] + 512);
            const float2 v0 = __half22float2(*(__half2*)&vu.x);
            const float2 v1 = __half22float2(*(__half2*)&vu.y);
            const float2 v2 = __half22float2(*(__half2*)&vu.z);
            const float2 v3 = __half22float2(*(__half2*)&vu.w);
            a[0] += p[j]*v0.x; a[1] += p[j]*v0.y;
            a[2] += p[j]*v1.x; a[3] += p[j]*v1.y;
            a[4] += p[j]*v2.x; a[5] += p[j]*v2.y;
            a[6] += p[j]*v3.x; a[7] += p[j]*v3.y;
        }
    }
    float* so = sOut + wid*256 + dil*64 + c0;
    *(float4*)(so)     = make_float4(a[0]*inv, a[1]*inv, a[2]*inv, a[3]*inv);
    *(float4*)(so + 4) = make_float4(a[4]*inv, a[5]*inv, a[6]*inv, a[7]*inv);
    __syncthreads();

    // fc mix + residual + LN(64): 2 passes of 4 pixels; thread = (px, channel)
    const int pxl_ = tid >> 6;        // 0..3
    const int c    = tid & 63;
    float fv[2][4];
#pragma unroll
    for (int it = 0; it < 2; it++){
        const int px = pxl_ + it*4;
        const float* sp = sOut + px*256;
        const float s0 = sp[c], s1 = sp[64 + c], s2 = sp[128 + c], s3 = sp[192 + c];
        const float sv[4] = {s0, s1, s2, s3};
        float sm[4], sq[4];
#pragma unroll
        for (int t = 0; t < 4; t++){
            fv[it][t] = fcw[t*4+0]*s0 + fcw[t*4+1]*s1 + fcw[t*4+2]*s2 + fcw[t*4+3]*s3
                        + fcb[t] + sv[t];
            sm[t] = fv[it][t]; sq[t] = fv[it][t]*fv[it][t];
        }
#pragma unroll
        for (int o = 16; o > 0; o >>= 1){
#pragma unroll
            for (int t = 0; t < 4; t++){
                sm[t] += __shfl_xor_sync(0xffffffffu, sm[t], o);
                sq[t] += __shfl_xor_sync(0xffffffffu, sq[t], o);
            }
        }
        if (lane == 0){
#pragma unroll
            for (int t = 0; t < 4; t++){ ssum[it][wid][t] = sm[t]; ssq[it][wid][t] = sq[t]; }
        }
    }
    __syncthreads();
    const float lg = lng[c], lb = lnb[c];
#pragma unroll
    for (int it = 0; it < 2; it++){
        const int px = pxl_ + it*4;
        __half* yo = y2 + (size_t)(blockIdx.x*8 + px)*256 + c;
#pragma unroll
        for (int t = 0; t < 4; t++){
            const float tot  = ssum[it][pxl_*2][t] + ssum[it][pxl_*2+1][t];
            const float totq = ssq[it][pxl_*2][t]  + ssq[it][pxl_*2+1][t];
            const float mu  = tot * (1.f/64.f);
            const float var = totq * (1.f/64.f) - mu*mu;
            yo[t*64] = __float2half_rn((fv[it][t] - mu) * rsqrtf(var + EPSF) * lg + lb);
        }
    }
}

// ---------------- launch ----------------
extern "C" void kernel_launch(void* const* d_in, const int* in_sizes, int n_in,
                              void* d_out, int out_size)
{
    const float* x      = (const float*)d_in[0];
    const float* qkv_w  = (const float*)d_in[1];
    const float* qkv_b  = (const float*)d_in[2];
    const float* fc_w   = (const float*)d_in[3];
    const float* fc_b   = (const float*)d_in[4];
    const float* ln_g   = (const float*)d_in[5];
    const float* ln_b   = (const float*)d_in[6];
    const float* proj_w = (const float*)d_in[7];
    const float* proj_b = (const float*)d_in[8];
    const float* w1     = (const float*)d_in[9];
    const float* bn1_g  = (const float*)d_in[10];
    const float* bn1_b  = (const float*)d_in[11];
    const float* bn1_m  = (const float*)d_in[12];
    const float* bn1_v  = (const float*)d_in[13];
    const float* w2     = (const float*)d_in[14];
    const float* bn2_g  = (const float*)d_in[15];
    const float* bn2_b  = (const float*)d_in[16];
    const float* bn2_m  = (const float*)d_in[17];
    const float* bn2_v  = (const float*)d_in[18];
    float* out = (float*)d_out;

    __half *xT, *qkv, *y2, *x1h, *hb, *gw;
    cudaGetSymbolAddress((void**)&xT,  g_xT);
    cudaGetSymbolAddress((void**)&qkv, g_qkv);
    cudaGetSymbolAddress((void**)&y2,  g_y2);
    cudaGetSymbolAddress((void**)&x1h, g_x1h);
    cudaGetSymbolAddress((void**)&hb,  g_h);
    cudaGetSymbolAddress((void**)&gw,  g_w);

    cudaFuncSetAttribute(gemm_mma<0>, cudaFuncAttributeMaxDynamicSharedMemorySize, SMEM_BYTES);
    cudaFuncSetAttribute(gemm_mma<1>, cudaFuncAttributeMaxDynamicSharedMemorySize, SMEM_BYTES);
    cudaFuncSetAttribute(gemm_mma<2>, cudaFuncAttributeMaxDynamicSharedMemorySize, SMEM_BYTES);
    cudaFuncSetAttribute(gemm_mma<3>, cudaFuncAttributeMaxDynamicSharedMemorySize, SMEM_BYTES);

    convw_k<<<512, 256>>>(qkv_w, proj_w, w1, w2, gw);
    transpose_k<<<dim3(HW/32, C_/32, B_), dim3(8, 32)>>>(x, xT);

    // 1) qkv = xT @ qkv_w^T + b : [51200][768] half
    gemm_mma<0><<<dim3(6, 400), 256, SMEM_BYTES>>>(
        xT, gw, qkv, nullptr, 256, 768, qkv_b, nullptr, nullptr, nullptr, nullptr, nullptr);

    // 2+3) attention + fc mix + LN (fused) -> y2 half
    attn_ln_k<<<NPIX/8, 256>>>(qkv, fc_w, fc_b, ln_g, ln_b, y2);

    // 4) x1 = y2 @ proj_w^T + proj_b + xT(half, coalesced) -> x1h
    gemm_mma<1><<<dim3(2, 400), 256, SMEM_BYTES>>>(
        y2, gw + 196608, x1h, nullptr, 256, 256, proj_b, xT, nullptr, nullptr, nullptr, nullptr);

    // 5) h = silu(bn1(x1 @ w1^T)) : [51200][512] half
    gemm_mma<2><<<dim3(4, 400), 256, SMEM_BYTES>>>(
        x1h, gw + 262144, hb, nullptr, 256, 512, nullptr, nullptr, bn1_g, bn1_b, bn1_m, bn1_v);

    // 6) out = x1(half) + bn2(h @ w2^T) -> [B][C][HW] float
    gemm_mma<3><<<dim3(2, 400), 256, SMEM_BYTES>>>(
        hb, gw + 393216, nullptr, out, 512, 256, nullptr, x1h, bn2_g, bn2_b, bn2_m, bn2_v);
}

// round 14
// speedup vs baseline: 1.2758x; 1.0332x over previous
#include <cuda_runtime.h>
#include <cuda_fp16.h>
#include <cstdint>
#include <math.h>

#define B_  8
#define C_  256
#define Hh  80
#define Ww  80
#define HW  6400
#define NPIX 51200
#define EPSF 1e-5f

#define KC 64
#define STAGES 3
#define TSTRH 72                 // smem row stride in halfs (144B): LDSM conflict-free
#define ST_B (128*TSTRH*2)       // 18432 B per operand stage
#define SMEM_BYTES (STAGES*2*ST_B)   // 110592 B per CTA

// ---------------- scratch ----------------
__device__ __half g_xT [(size_t)NPIX*256];
__device__ __half g_qkv[(size_t)NPIX*768];
__device__ __half g_y2 [(size_t)NPIX*256];
__device__ __half g_x1h[(size_t)NPIX*256];
__device__ __half g_h  [(size_t)NPIX*512];
__device__ __half g_w  [524288];

// ---------------- helpers ----------------
__device__ __forceinline__ uint32_t s2u(const void* p){
    uint32_t a; asm("{ .reg .u64 t; cvta.to.shared.u64 t, %1; cvt.u32.u64 %0, t; }" : "=r"(a) : "l"(p)); return a;
}
#define CPA16(d,s) asm volatile("cp.async.cg.shared.global [%0], [%1], 16;" :: "r"(d), "l"(s))
#define CPCOMMIT() asm volatile("cp.async.commit_group;" ::: "memory")
#define CPWAIT(n)  asm volatile("cp.async.wait_group %0;" :: "n"(n) : "memory")
#define LDSM4(r0,r1,r2,r3,a) \
    asm volatile("ldmatrix.sync.aligned.m8n8.x4.shared.b16 {%0,%1,%2,%3}, [%4];" \
        : "=r"(r0), "=r"(r1), "=r"(r2), "=r"(r3) : "r"(a))

__device__ __forceinline__ void mma16(float* d, const uint32_t* a, uint32_t b0, uint32_t b1){
    asm volatile("mma.sync.aligned.m16n8k16.row.col.f32.f16.f16.f32 "
        "{%0,%1,%2,%3}, {%4,%5,%6,%7}, {%8,%9}, {%0,%1,%2,%3};"
        : "+f"(d[0]), "+f"(d[1]), "+f"(d[2]), "+f"(d[3])
        : "r"(a[0]), "r"(a[1]), "r"(a[2]), "r"(a[3]), "r"(b0), "r"(b1));
}

// ---------------- fp16 mma.sync GEMM, 128x128 tile, 8 warps, KC=64, 3 stages ----------------
// MODE 0: Ch = acc + bias[n]                       -> qkv half (Cstride 768)
// MODE 1: Ch = half(acc+bias+res(half [pix][c]))   -> x1h
// MODE 2: Ch = half(silu(acc*sc+sh))               -> h half (Cstride 512)
// MODE 3: Cf = acc*sc+sh + res(half) -> out[b][n][pixl] (smem-staged transposed store)
template<int MODE>
__global__ __launch_bounds__(256, 2) void gemm_mma(
    const __half* __restrict__ A, const __half* __restrict__ Bw,
    __half* __restrict__ Ch, float* __restrict__ Cf, int Ktot, int Cstride,
    const float* __restrict__ bias, const __half* __restrict__ resh,
    const float* __restrict__ gg, const float* __restrict__ bb,
    const float* __restrict__ mm, const float* __restrict__ vv)
{
    extern __shared__ float smemf[];
    const uint32_t smem_b = s2u(smemf);

    const int tid  = threadIdx.x;
    const int wid  = tid >> 5;
    const int lane = tid & 31;
    const int wm   = wid & 1;         // 2 warps in M (64 rows)
    const int wn   = wid >> 1;        // 4 warps in N (32 cols)
    const int lr   = lane >> 2;
    const int lc   = lane & 3;
    const int m0   = blockIdx.y * 128;
    const int n0   = blockIdx.x * 128;

    const uint32_t aoff = (uint32_t)(((wm*64 + ((lane>>3)&1)*8 + (lane&7))*TSTRH + (lane>>4)*8) * 2);
    const uint32_t boff = (uint32_t)(((wn*32 + (lane>>4)*8 + (lane&7))*TSTRH + ((lane>>3)&1)*8) * 2);

    float d[4][4][4];
#pragma unroll
    for (int i = 0; i < 4; i++)
#pragma unroll
        for (int j = 0; j < 4; j++)
#pragma unroll
            for (int e = 0; e < 4; e++) d[i][j][e] = 0.f;

    const int nch = Ktot / KC;

    auto load = [&](int cc){
        const int s = cc % STAGES;
        const __half* Ab = A + (size_t)m0 * Ktot + cc*KC;
        const uint32_t da = smem_b + (2*s)*ST_B;
#pragma unroll
        for (int t = 0; t < 4; t++){
            int i = tid + t*256;
            int r = i >> 3, c = i & 7;
            CPA16(da + r*TSTRH*2 + c*16, (const void*)(Ab + (size_t)r*Ktot + c*8));
        }
        const __half* Bb = Bw + (size_t)n0 * Ktot + cc*KC;
        const uint32_t db = smem_b + (2*s+1)*ST_B;
#pragma unroll
        for (int t = 0; t < 4; t++){
            int i = tid + t*256;
            int r = i >> 3, c = i & 7;
            CPA16(db + r*TSTRH*2 + c*16, (const void*)(Bb + (size_t)r*Ktot + c*8));
        }
        CPCOMMIT();
    };

    load(0); load(1);

    for (int cc = 0; cc < nch; cc++){
        const int rem = nch - 1 - cc;
        if (rem >= 1) CPWAIT(1);
        else          CPWAIT(0);
        __syncthreads();
        if (cc + 2 < nch) load(cc + 2);

        const int s = cc % STAGES;
        const uint32_t aBase = smem_b + (2*s)*ST_B + aoff;
        const uint32_t bBase = smem_b + (2*s+1)*ST_B + boff;
#pragma unroll
        for (int kk = 0; kk < 4; kk++){
            uint32_t a[4][4], bf[2][4];
#pragma unroll
            for (int mi = 0; mi < 4; mi++)
                LDSM4(a[mi][0], a[mi][1], a[mi][2], a[mi][3],
                      aBase + mi*(16*TSTRH*2) + kk*32);
#pragma unroll
            for (int np = 0; np < 2; np++)
                LDSM4(bf[np][0], bf[np][1], bf[np][2], bf[np][3],
                      bBase + np*(16*TSTRH*2) + kk*32);
#pragma unroll
            for (int np = 0; np < 2; np++)
#pragma unroll
                for (int mi = 0; mi < 4; mi++){
                    mma16(d[mi][2*np],   a[mi], bf[np][0], bf[np][1]);
                    mma16(d[mi][2*np+1], a[mi], bf[np][2], bf[np][3]);
                }
        }
    }

    // ---------------- epilogue ----------------
    const int lc2 = lc * 2;

    if (MODE != 3){
#pragma unroll
        for (int mi = 0; mi < 4; mi++){
#pragma unroll
            for (int rr = 0; rr < 2; rr++){
                const int rl = wm*64 + mi*16 + lr + rr*8;
                const int r  = m0 + rl;
                __half* crow = Ch + (size_t)r*Cstride + n0 + wn*32;
                const __half* rrow = (MODE == 1) ? resh + (size_t)r*256 + n0 + wn*32 : (const __half*)0;
#pragma unroll
                for (int ni = 0; ni < 4; ni++){
                    const int c = ni*8 + lc2;
                    const int gc = n0 + wn*32 + c;
                    float v0 = d[mi][ni][rr*2+0];
                    float v1 = d[mi][ni][rr*2+1];
                    if (MODE == 0){
                        v0 += bias[gc]; v1 += bias[gc+1];
                        *(__half2*)(crow + c) = __floats2half2_rn(v0, v1);
                    } else if (MODE == 1){
                        const float2 rf = __half22float2(*(const __half2*)(rrow + c));
                        v0 += bias[gc]   + rf.x;
                        v1 += bias[gc+1] + rf.y;
                        *(__half2*)(crow + c) = __floats2half2_rn(v0, v1);
                    } else { // MODE 2
                        float i0 = gg[gc]   * rsqrtf(vv[gc]   + EPSF);
                        float i1 = gg[gc+1] * rsqrtf(vv[gc+1] + EPSF);
                        v0 = v0*i0 + (bb[gc]   - mm[gc]  *i0);
                        v1 = v1*i1 + (bb[gc+1] - mm[gc+1]*i1);
                        v0 = v0 * __frcp_rn(1.f + __expf(-v0));
                        v1 = v1 * __frcp_rn(1.f + __expf(-v1));
                        *(__half2*)(crow + c) = __floats2half2_rn(v0, v1);
                    }
                }
            }
        }
    } else {
        // MODE 3: bn2 + residual (half x1), smem-transposed coalesced store to [b][c][hw]
        __syncthreads();
        float* stg = smemf + wid * (64*33);
#pragma unroll
        for (int ni = 0; ni < 4; ni++){
            const int gc = n0 + wn*32 + ni*8 + lc2;
            const float i0 = gg[gc]   * rsqrtf(vv[gc]   + EPSF);
            const float i1 = gg[gc+1] * rsqrtf(vv[gc+1] + EPSF);
            const float s0 = bb[gc]   - mm[gc]  *i0;
            const float s1 = bb[gc+1] - mm[gc+1]*i1;
#pragma unroll
            for (int mi = 0; mi < 4; mi++){
#pragma unroll
                for (int rr = 0; rr < 2; rr++){
                    const int lrow = mi*16 + lr + rr*8;
                    const int grow = m0 + wm*64 + lrow;
                    const float2 rf = __half22float2(*(const __half2*)(resh + (size_t)grow*256 + gc));
                    stg[lrow*33 + ni*8 + lc2]     = d[mi][ni][rr*2+0]*i0 + s0 + rf.x;
                    stg[lrow*33 + ni*8 + lc2 + 1] = d[mi][ni][rr*2+1]*i1 + s1 + rf.y;
                }
            }
        }
        __syncwarp();
        const int pix0 = m0 + wm*64;
        const int bidx = pix0 / HW;
        const int pixl = pix0 - bidx*HW;
        float* ob = Cf + (size_t)bidx*C_*HW + pixl;
#pragma unroll
        for (int n = 0; n < 32; n++){
            const int gc = n0 + wn*32 + n;
            ob[(size_t)gc*HW + lane]      = stg[lane*33 + n];
            ob[(size_t)gc*HW + lane + 32] = stg[(lane+32)*33 + n];
        }
    }
}

// ---------------- transpose x [B][C][HW] -> xT half (vectorized) ----------------
__global__ __launch_bounds__(256) void transpose_k(const float* __restrict__ x,
                                                   __half* __restrict__ xT)
{
    __shared__ float t[32][33];
    const int b = blockIdx.z;
    const int hw0 = blockIdx.x * 32, c0 = blockIdx.y * 32;
    const int tx = threadIdx.x;   // 0..7
    const int ty = threadIdx.y;   // 0..31

    const float4 v = *(const float4*)(x + (size_t)b*C_*HW + (size_t)(c0+ty)*HW + hw0 + tx*4);
    t[ty][tx*4+0] = v.x; t[ty][tx*4+1] = v.y; t[ty][tx*4+2] = v.z; t[ty][tx*4+3] = v.w;
    __syncthreads();

    const float f0 = t[tx*4+0][ty], f1 = t[tx*4+1][ty];
    const float f2 = t[tx*4+2][ty], f3 = t[tx*4+3][ty];
    uint2 o;
    __half2 h01 = __floats2half2_rn(f0, f1);
    __half2 h23 = __floats2half2_rn(f2, f3);
    o.x = *(uint32_t*)&h01; o.y = *(uint32_t*)&h23;
    *(uint2*)(xT + (size_t)(b*HW + hw0 + ty)*256 + c0 + tx*4) = o;
}

// ---------------- convert weights to half (vectorized) ----------------
__global__ __launch_bounds__(256) void convw_k(
    const float* __restrict__ qkvw, const float* __restrict__ projw,
    const float* __restrict__ w1, const float* __restrict__ w2, __half* __restrict__ gw)
{
    int i4 = blockIdx.x * 256 + threadIdx.x;
    int i = i4 * 4;
    const float* src;
    if (i < 196608)      src = qkvw + i;
    else if (i < 262144) src = projw + (i - 196608);
    else if (i < 393216) src = w1 + (i - 262144);
    else                 src = w2 + (i - 393216);
    const float4 v = *(const float4*)src;
    __half2 h01 = __floats2half2_rn(v.x, v.y);
    __half2 h23 = __floats2half2_rn(v.z, v.w);
    uint2 o; o.x = *(uint32_t*)&h01; o.y = *(uint32_t*)&h23;
    *(uint2*)(gw + i) = o;
}

// ---------------- fused attention + fc-mix + LayerNorm ----------------
// Attention: 8 warps = 8 pixels; warp = 4 dilations x 8 lanes, 8 ch/lane.
// LN: thread = (px4, t-slot, channel-quad); 16-lane groups reduce fully in-warp.
__global__ __launch_bounds__(256) void attn_ln_k(
    const __half* __restrict__ qkv,
    const float* __restrict__ fcw, const float* __restrict__ fcb,
    const float* __restrict__ lng, const float* __restrict__ lnb,
    __half* __restrict__ y2)
{
    __shared__ float sOut[2048];      // [8 pixels][4 dil][64 ch]

    const int tid  = threadIdx.x;
    const int wid  = tid >> 5;        // pixel in block
    const int lane = tid & 31;
    const int dil  = lane >> 3;
    const int c0   = (lane & 7) * 8;
    const int pix  = blockIdx.x * 8 + wid;
    const int b    = pix / HW;
    const int pixl = pix - b * HW;
    const int y    = pixl / Ww;
    const int x    = pixl - y * Ww;
    const int r    = 1 << dil;

    const __half* base = qkv + (size_t)b * HW * 768 + dil*64 + c0;

    int offs[9]; unsigned vm = 0;
#pragma unroll
    for (int j = 0; j < 9; j++){
        const int yy = y + (j/3 - 1) * r;
        const int xx = x + (j%3 - 1) * r;
        offs[j] = (yy*Ww + xx) * 768;
        if ((unsigned)yy < (unsigned)Hh && (unsigned)xx < (unsigned)Ww) vm |= 1u << j;
    }

    uint4 qu = *(const uint4*)(base + (size_t)pixl*768);
    const __half2 qh0 = *(__half2*)&qu.x;
    const __half2 qh1 = *(__half2*)&qu.y;
    const __half2 qh2 = *(__half2*)&qu.z;
    const __half2 qh3 = *(__half2*)&qu.w;

    float sc[9];
#pragma unroll
    for (int j = 0; j < 9; j++){
        float s = 0.f;
        if (vm & (1u << j)){
            uint4 ku = *(const uint4*)(base + offs[j] + 256);
            __half2 a0 = __hmul2(qh0, *(__half2*)&ku.x);
            a0 = __hfma2(qh1, *(__half2*)&ku.y, a0);
            __half2 a1 = __hmul2(qh2, *(__half2*)&ku.z);
            a1 = __hfma2(qh3, *(__half2*)&ku.w, a1);
            s = __low2float(a0) + __high2float(a0) + __low2float(a1) + __high2float(a1);
        }
#pragma unroll
        for (int o = 4; o > 0; o >>= 1) s += __shfl_xor_sync(0xffffffffu, s, o);
        sc[j] = s * 0.125f;
    }

    float mx = sc[0];
#pragma unroll
    for (int j = 1; j < 9; j++) mx = fmaxf(mx, sc[j]);
    float p[9], sum = 0.f;
#pragma unroll
    for (int j = 0; j < 9; j++){ p[j] = __expf(sc[j] - mx); sum += p[j]; }
    const float inv = __frcp_rn(sum);

    float a[8];
#pragma unroll
    for (int e = 0; e < 8; e++) a[e] = 0.f;
#pragma unroll
    for (int j = 0; j < 9; j++){
        if (vm & (1u << j)){
            uint4 vu = *(const uint4*)(base + offs[j] + 512);
            const float2 v0 = __half22float2(*(__half2*)&vu.x);
            const float2 v1 = __half22float2(*(__half2*)&vu.y);
            const float2 v2 = __half22float2(*(__half2*)&vu.z);
            const float2 v3 = __half22float2(*(__half2*)&vu.w);
            a[0] += p[j]*v0.x; a[1] += p[j]*v0.y;
            a[2] += p[j]*v1.x; a[3] += p[j]*v1.y;
            a[4] += p[j]*v2.x; a[5] += p[j]*v2.y;
            a[6] += p[j]*v3.x; a[7] += p[j]*v3.y;
        }
    }
    float* so = sOut + wid*256 + dil*64 + c0;
    *(float4*)(so)     = make_float4(a[0]*inv, a[1]*inv, a[2]*inv, a[3]*inv);
    *(float4*)(so + 4) = make_float4(a[4]*inv, a[5]*inv, a[6]*inv, a[7]*inv);
    __syncthreads();

    // fc mix + residual + LN(64): thread = (px4 in 0..3, ts in 0..3, cq in 0..15)
    // 16-lane groups (same px,ts) reduce fully within the warp. 2 passes over pixels.
    const int px4 = tid >> 6;         // 0..3
    const int ts  = (tid >> 4) & 3;   // dilation slot
    const int cq  = tid & 15;         // channel quad
    const int c   = cq * 4;
    const float w0 = fcw[ts*4+0], w1_ = fcw[ts*4+1], w2_ = fcw[ts*4+2], w3 = fcw[ts*4+3];
    const float fb = fcb[ts];
    const float4 lg = *(const float4*)(lng + c);
    const float4 lb = *(const float4*)(lnb + c);

#pragma unroll
    for (int it = 0; it < 2; it++){
        const int px = px4 + it*4;
        const float* sp = sOut + px*256 + c;
        const float4 s0 = *(const float4*)(sp);
        const float4 s1 = *(const float4*)(sp + 64);
        const float4 s2 = *(const float4*)(sp + 128);
        const float4 s3 = *(const float4*)(sp + 192);
        const float4 own = (ts == 0) ? s0 : (ts == 1) ? s1 : (ts == 2) ? s2 : s3;
        float f[4];
        f[0] = w0*s0.x + w1_*s1.x + w2_*s2.x + w3*s3.x + fb + own.x;
        f[1] = w0*s0.y + w1_*s1.y + w2_*s2.y + w3*s3.y + fb + own.y;
        f[2] = w0*s0.z + w1_*s1.z + w2_*s2.z + w3*s3.z + fb + own.z;
        f[3] = w0*s0.w + w1_*s1.w + w2_*s2.w + w3*s3.w + fb + own.w;

        float sm = f[0] + f[1] + f[2] + f[3];
        float sq = f[0]*f[0] + f[1]*f[1] + f[2]*f[2] + f[3]*f[3];
#pragma unroll
        for (int o = 8; o > 0; o >>= 1){
            sm += __shfl_xor_sync(0xffffffffu, sm, o);
            sq += __shfl_xor_sync(0xffffffffu, sq, o);
        }
        const float mu  = sm * (1.f/64.f);
        const float var = sq * (1.f/64.f) - mu*mu;
        const float rs  = rsqrtf(var + EPSF);
        __half2 h01 = __floats2half2_rn((f[0]-mu)*rs*lg.x + lb.x, (f[1]-mu)*rs*lg.y + lb.y);
        __half2 h23 = __floats2half2_rn((f[2]-mu)*rs*lg.z + lb.z, (f[3]-mu)*rs*lg.w + lb.w);
        uint2 o2; o2.x = *(uint32_t*)&h01; o2.y = *(uint32_t*)&h23;
        *(uint2*)(y2 + (size_t)(blockIdx.x*8 + px)*256 + ts*64 + c) = o2;
    }
}

// ---------------- launch ----------------
extern "C" void kernel_launch(void* const* d_in, const int* in_sizes, int n_in,
                              void* d_out, int out_size)
{
    const float* x      = (const float*)d_in[0];
    const float* qkv_w  = (const float*)d_in[1];
    const float* qkv_b  = (const float*)d_in[2];
    const float* fc_w   = (const float*)d_in[3];
    const float* fc_b   = (const float*)d_in[4];
    const float* ln_g   = (const float*)d_in[5];
    const float* ln_b   = (const float*)d_in[6];
    const float* proj_w = (const float*)d_in[7];
    const float* proj_b = (const float*)d_in[8];
    const float* w1     = (const float*)d_in[9];
    const float* bn1_g  = (const float*)d_in[10];
    const float* bn1_b  = (const float*)d_in[11];
    const float* bn1_m  = (const float*)d_in[12];
    const float* bn1_v  = (const float*)d_in[13];
    const float* w2     = (const float*)d_in[14];
    const float* bn2_g  = (const float*)d_in[15];
    const float* bn2_b  = (const float*)d_in[16];
    const float* bn2_m  = (const float*)d_in[17];
    const float* bn2_v  = (const float*)d_in[18];
    float* out = (float*)d_out;

    __half *xT, *qkv, *y2, *x1h, *hb, *gw;
    cudaGetSymbolAddress((void**)&xT,  g_xT);
    cudaGetSymbolAddress((void**)&qkv, g_qkv);
    cudaGetSymbolAddress((void**)&y2,  g_y2);
    cudaGetSymbolAddress((void**)&x1h, g_x1h);
    cudaGetSymbolAddress((void**)&hb,  g_h);
    cudaGetSymbolAddress((void**)&gw,  g_w);

    cudaFuncSetAttribute(gemm_mma<0>, cudaFuncAttributeMaxDynamicSharedMemorySize, SMEM_BYTES);
    cudaFuncSetAttribute(gemm_mma<1>, cudaFuncAttributeMaxDynamicSharedMemorySize, SMEM_BYTES);
    cudaFuncSetAttribute(gemm_mma<2>, cudaFuncAttributeMaxDynamicSharedMemorySize, SMEM_BYTES);
    cudaFuncSetAttribute(gemm_mma<3>, cudaFuncAttributeMaxDynamicSharedMemorySize, SMEM_BYTES);

    convw_k<<<512, 256>>>(qkv_w, proj_w, w1, w2, gw);
    transpose_k<<<dim3(HW/32, C_/32, B_), dim3(8, 32)>>>(x, xT);

    // 1) qkv = xT @ qkv_w^T + b : [51200][768] half
    gemm_mma<0><<<dim3(6, 400), 256, SMEM_BYTES>>>(
        xT, gw, qkv, nullptr, 256, 768, qkv_b, nullptr, nullptr, nullptr, nullptr, nullptr);

    // 2+3) attention + fc mix + LN (fused) -> y2 half
    attn_ln_k<<<NPIX/8, 256>>>(qkv, fc_w, fc_b, ln_g, ln_b, y2);

    // 4) x1 = y2 @ proj_w^T + proj_b + xT(half) -> x1h
    gemm_mma<1><<<dim3(2, 400), 256, SMEM_BYTES>>>(
        y2, gw + 196608, x1h, nullptr, 256, 256, proj_b, xT, nullptr, nullptr, nullptr, nullptr);

    // 5) h = silu(bn1(x1 @ w1^T)) : [51200][512] half
    gemm_mma<2><<<dim3(4, 400), 256, SMEM_BYTES>>>(
        x1h, gw + 262144, hb, nullptr, 256, 512, nullptr, nullptr, bn1_g, bn1_b, bn1_m, bn1_v);

    // 6) out = x1(half) + bn2(h @ w2^T) -> [B][C][HW] float
    gemm_mma<3><<<dim3(2, 400), 256, SMEM_BYTES>>>(
        hb, gw + 393216, nullptr, out, 512, 256, nullptr, x1h, bn2_g, bn2_b, bn2_m, bn2_v);
}

// round 16
// speedup vs baseline: 1.2993x; 1.0184x over previous
#include <cuda_runtime.h>
#include <cuda_fp16.h>
#include <cstdint>
#include <math.h>

#define B_  8
#define C_  256
#define Hh  80
#define Ww  80
#define HW  6400
#define NPIX 51200
#define EPSF 1e-5f

#define KC 64
#define STAGES 3
#define TSTRH 72                 // smem row stride in halfs (144B): LDSM conflict-free
#define ST_B (128*TSTRH*2)       // 18432 B per operand stage
#define SMEM_BYTES (STAGES*2*ST_B)   // 110592 B per CTA

// ---------------- scratch ----------------
__device__ __half g_xT [(size_t)NPIX*256];
__device__ __half g_qkv[(size_t)NPIX*768];
__device__ __half g_y2 [(size_t)NPIX*256];
__device__ __half g_x1h[(size_t)NPIX*256];
__device__ __half g_h  [(size_t)NPIX*512];
__device__ __half g_w  [524288];

// ---------------- helpers ----------------
__device__ __forceinline__ uint32_t s2u(const void* p){
    uint32_t a; asm("{ .reg .u64 t; cvta.to.shared.u64 t, %1; cvt.u32.u64 %0, t; }" : "=r"(a) : "l"(p)); return a;
}
#define CPA16(d,s) asm volatile("cp.async.cg.shared.global [%0], [%1], 16;" :: "r"(d), "l"(s))
#define CPCOMMIT() asm volatile("cp.async.commit_group;" ::: "memory")
#define CPWAIT(n)  asm volatile("cp.async.wait_group %0;" :: "n"(n) : "memory")
#define LDSM4(r0,r1,r2,r3,a) \
    asm volatile("ldmatrix.sync.aligned.m8n8.x4.shared.b16 {%0,%1,%2,%3}, [%4];" \
        : "=r"(r0), "=r"(r1), "=r"(r2), "=r"(r3) : "r"(a))

__device__ __forceinline__ void mma16(float* d, const uint32_t* a, uint32_t b0, uint32_t b1){
    asm volatile("mma.sync.aligned.m16n8k16.row.col.f32.f16.f16.f32 "
        "{%0,%1,%2,%3}, {%4,%5,%6,%7}, {%8,%9}, {%0,%1,%2,%3};"
        : "+f"(d[0]), "+f"(d[1]), "+f"(d[2]), "+f"(d[3])
        : "r"(a[0]), "r"(a[1]), "r"(a[2]), "r"(a[3]), "r"(b0), "r"(b1));
}

// ---------------- fp16 mma.sync GEMM, 128x128 tile, 8 warps, KC=64, 3 stages ----------------
// MODE 0: Ch = acc + bias[n]                       -> qkv half (Cstride 768)
// MODE 1: Ch = half(acc+bias+res(half [pix][c]))   -> x1h
// MODE 2: Ch = half(silu(acc*sc+sh))               -> h half (Cstride 512)
// MODE 3: Cf = acc*sc+sh + res(half) -> out[b][n][pixl] (smem-staged transposed store)
template<int MODE>
__global__ __launch_bounds__(256, 2) void gemm_mma(
    const __half* __restrict__ A, const __half* __restrict__ Bw,
    __half* __restrict__ Ch, float* __restrict__ Cf, int Ktot, int Cstride,
    const float* __restrict__ bias, const __half* __restrict__ resh,
    const float* __restrict__ gg, const float* __restrict__ bb,
    const float* __restrict__ mm, const float* __restrict__ vv)
{
    extern __shared__ float smemf[];
    const uint32_t smem_b = s2u(smemf);

    const int tid  = threadIdx.x;
    const int wid  = tid >> 5;
    const int lane = tid & 31;
    const int wm   = wid & 1;         // 2 warps in M (64 rows)
    const int wn   = wid >> 1;        // 4 warps in N (32 cols)
    const int lr   = lane >> 2;
    const int lc   = lane & 3;
    const int m0   = blockIdx.y * 128;
    const int n0   = blockIdx.x * 128;

    const uint32_t aoff = (uint32_t)(((wm*64 + ((lane>>3)&1)*8 + (lane&7))*TSTRH + (lane>>4)*8) * 2);
    const uint32_t boff = (uint32_t)(((wn*32 + (lane>>4)*8 + (lane&7))*TSTRH + ((lane>>3)&1)*8) * 2);

    float d[4][4][4];
#pragma unroll
    for (int i = 0; i < 4; i++)
#pragma unroll
        for (int j = 0; j < 4; j++)
#pragma unroll
            for (int e = 0; e < 4; e++) d[i][j][e] = 0.f;

    const int nch = Ktot / KC;

    auto load = [&](int cc){
        const int s = cc % STAGES;
        const __half* Ab = A + (size_t)m0 * Ktot + cc*KC;
        const uint32_t da = smem_b + (2*s)*ST_B;
#pragma unroll
        for (int t = 0; t < 4; t++){
            int i = tid + t*256;
            int r = i >> 3, c = i & 7;
            CPA16(da + r*TSTRH*2 + c*16, (const void*)(Ab + (size_t)r*Ktot + c*8));
        }
        const __half* Bb = Bw + (size_t)n0 * Ktot + cc*KC;
        const uint32_t db = smem_b + (2*s+1)*ST_B;
#pragma unroll
        for (int t = 0; t < 4; t++){
            int i = tid + t*256;
            int r = i >> 3, c = i & 7;
            CPA16(db + r*TSTRH*2 + c*16, (const void*)(Bb + (size_t)r*Ktot + c*8));
        }
        CPCOMMIT();
    };

    load(0); load(1);

    for (int cc = 0; cc < nch; cc++){
        const int rem = nch - 1 - cc;
        if (rem >= 1) CPWAIT(1);
        else          CPWAIT(0);
        __syncthreads();
        if (cc + 2 < nch) load(cc + 2);

        const int s = cc % STAGES;
        const uint32_t aBase = smem_b + (2*s)*ST_B + aoff;
        const uint32_t bBase = smem_b + (2*s+1)*ST_B + boff;
#pragma unroll
        for (int kk = 0; kk < 4; kk++){
            uint32_t a[4][4], bf[2][4];
#pragma unroll
            for (int mi = 0; mi < 4; mi++)
                LDSM4(a[mi][0], a[mi][1], a[mi][2], a[mi][3],
                      aBase + mi*(16*TSTRH*2) + kk*32);
#pragma unroll
            for (int np = 0; np < 2; np++)
                LDSM4(bf[np][0], bf[np][1], bf[np][2], bf[np][3],
                      bBase + np*(16*TSTRH*2) + kk*32);
#pragma unroll
            for (int np = 0; np < 2; np++)
#pragma unroll
                for (int mi = 0; mi < 4; mi++){
                    mma16(d[mi][2*np],   a[mi], bf[np][0], bf[np][1]);
                    mma16(d[mi][2*np+1], a[mi], bf[np][2], bf[np][3]);
                }
        }
    }

    // ---------------- epilogue ----------------
    const int lc2 = lc * 2;

    if (MODE != 3){
#pragma unroll
        for (int mi = 0; mi < 4; mi++){
#pragma unroll
            for (int rr = 0; rr < 2; rr++){
                const int rl = wm*64 + mi*16 + lr + rr*8;
                const int r  = m0 + rl;
                __half* crow = Ch + (size_t)r*Cstride + n0 + wn*32;
                const __half* rrow = (MODE == 1) ? resh + (size_t)r*256 + n0 + wn*32 : (const __half*)0;
#pragma unroll
                for (int ni = 0; ni < 4; ni++){
                    const int c = ni*8 + lc2;
                    const int gc = n0 + wn*32 + c;
                    float v0 = d[mi][ni][rr*2+0];
                    float v1 = d[mi][ni][rr*2+1];
                    if (MODE == 0){
                        v0 += bias[gc]; v1 += bias[gc+1];
                        *(__half2*)(crow + c) = __floats2half2_rn(v0, v1);
                    } else if (MODE == 1){
                        const float2 rf = __half22float2(*(const __half2*)(rrow + c));
                        v0 += bias[gc]   + rf.x;
                        v1 += bias[gc+1] + rf.y;
                        *(__half2*)(crow + c) = __floats2half2_rn(v0, v1);
                    } else { // MODE 2
                        float i0 = gg[gc]   * rsqrtf(vv[gc]   + EPSF);
                        float i1 = gg[gc+1] * rsqrtf(vv[gc+1] + EPSF);
                        v0 = v0*i0 + (bb[gc]   - mm[gc]  *i0);
                        v1 = v1*i1 + (bb[gc+1] - mm[gc+1]*i1);
                        v0 = v0 * __frcp_rn(1.f + __expf(-v0));
                        v1 = v1 * __frcp_rn(1.f + __expf(-v1));
                        *(__half2*)(crow + c) = __floats2half2_rn(v0, v1);
                    }
                }
            }
        }
    } else {
        // MODE 3: bn2 + residual (half x1), smem-transposed coalesced store to [b][c][hw]
        __syncthreads();
        float* stg = smemf + wid * (64*33);
#pragma unroll
        for (int ni = 0; ni < 4; ni++){
            const int gc = n0 + wn*32 + ni*8 + lc2;
            const float i0 = gg[gc]   * rsqrtf(vv[gc]   + EPSF);
            const float i1 = gg[gc+1] * rsqrtf(vv[gc+1] + EPSF);
            const float s0 = bb[gc]   - mm[gc]  *i0;
            const float s1 = bb[gc+1] - mm[gc+1]*i1;
#pragma unroll
            for (int mi = 0; mi < 4; mi++){
#pragma unroll
                for (int rr = 0; rr < 2; rr++){
                    const int lrow = mi*16 + lr + rr*8;
                    const int grow = m0 + wm*64 + lrow;
                    const float2 rf = __half22float2(*(const __half2*)(resh + (size_t)grow*256 + gc));
                    stg[lrow*33 + ni*8 + lc2]     = d[mi][ni][rr*2+0]*i0 + s0 + rf.x;
                    stg[lrow*33 + ni*8 + lc2 + 1] = d[mi][ni][rr*2+1]*i1 + s1 + rf.y;
                }
            }
        }
        __syncwarp();
        const int pix0 = m0 + wm*64;
        const int bidx = pix0 / HW;
        const int pixl = pix0 - bidx*HW;
        float* ob = Cf + (size_t)bidx*C_*HW + pixl;
#pragma unroll
        for (int n = 0; n < 32; n++){
            const int gc = n0 + wn*32 + n;
            ob[(size_t)gc*HW + lane]      = stg[lane*33 + n];
            ob[(size_t)gc*HW + lane + 32] = stg[(lane+32)*33 + n];
        }
    }
}

// ---------------- prep: transpose x -> xT half AND convert weights (one launch) ----------------
__global__ __launch_bounds__(256) void prep_k(const float* __restrict__ x,
                                              __half* __restrict__ xT,
                                              const float* __restrict__ qkvw,
                                              const float* __restrict__ projw,
                                              const float* __restrict__ w1,
                                              const float* __restrict__ w2,
                                              __half* __restrict__ gw)
{
    const int blk = blockIdx.x;
    if (blk < 1600){
        // blk = b*200 + ct*25 + ht : b in 0..7, ct in 0..7, ht in 0..24
        const int b  = blk / 200;
        const int rm = blk - b*200;
        const int ct = rm / 25;
        const int ht = rm - ct*25;
        __shared__ float t[32][33];
        const int tid = threadIdx.x;
        const int tx = tid & 7;       // 0..7 (float4 within 32 hw)
        const int ty = tid >> 3;      // 0..31 (channel)
        const int c0 = ct * 32;
        for (int sub = 0; sub < 8; sub++){
            const int hw0 = ht*256 + sub*32;
            const float4 v = *(const float4*)(x + (size_t)b*C_*HW + (size_t)(c0+ty)*HW + hw0 + tx*4);
            t[ty][tx*4+0] = v.x; t[ty][tx*4+1] = v.y; t[ty][tx*4+2] = v.z; t[ty][tx*4+3] = v.w;
            __syncthreads();
            const float f0 = t[tx*4+0][ty], f1 = t[tx*4+1][ty];
            const float f2 = t[tx*4+2][ty], f3 = t[tx*4+3][ty];
            uint2 o;
            __half2 h01 = __floats2half2_rn(f0, f1);
            __half2 h23 = __floats2half2_rn(f2, f3);
            o.x = *(uint32_t*)&h01; o.y = *(uint32_t*)&h23;
            *(uint2*)(xT + (size_t)(b*HW + hw0 + ty)*256 + c0 + tx*4) = o;
            __syncthreads();
        }
    } else {
        const int i4 = (blk - 1600) * 256 + threadIdx.x;   // 131072 float4s total
        const int i = i4 * 4;
        const float* src;
        if (i < 196608)      src = qkvw + i;
        else if (i < 262144) src = projw + (i - 196608);
        else if (i < 393216) src = w1 + (i - 262144);
        else                 src = w2 + (i - 393216);
        const float4 v = *(const float4*)src;
        __half2 h01 = __floats2half2_rn(v.x, v.y);
        __half2 h23 = __floats2half2_rn(v.z, v.w);
        uint2 o; o.x = *(uint32_t*)&h01; o.y = *(uint32_t*)&h23;
        *(uint2*)(gw + i) = o;
    }
}

// ---------------- fused attention + fc-mix + LayerNorm ----------------
// Attention: 8 warps = 8 pixels; warp = 4 dilations x 8 lanes, 8 ch/lane.
// k-vectors batch-loaded (MLP=9). NOTE: reference zero-pads k/v — out-of-bounds
// neighbors score 0 and PARTICIPATE in the softmax denominator (no masking!).
__global__ __launch_bounds__(256) void attn_ln_k(
    const __half* __restrict__ qkv,
    const float* __restrict__ fcw, const float* __restrict__ fcb,
    const float* __restrict__ lng, const float* __restrict__ lnb,
    __half* __restrict__ y2)
{
    __shared__ float sOut[2048];      // [8 pixels][4 dil][64 ch]

    const int tid  = threadIdx.x;
    const int wid  = tid >> 5;        // pixel in block
    const int lane = tid & 31;
    const int dil  = lane >> 3;
    const int c0   = (lane & 7) * 8;
    const int pix  = blockIdx.x * 8 + wid;
    const int b    = pix / HW;
    const int pixl = pix - b * HW;
    const int y    = pixl / Ww;
    const int x    = pixl - y * Ww;
    const int r    = 1 << dil;

    const __half* base = qkv + (size_t)b * HW * 768 + dil*64 + c0;

    int offs[9]; unsigned vm = 0;
#pragma unroll
    for (int j = 0; j < 9; j++){
        const int yy = y + (j/3 - 1) * r;
        const int xx = x + (j%3 - 1) * r;
        offs[j] = (yy*Ww + xx) * 768;
        if ((unsigned)yy < (unsigned)Hh && (unsigned)xx < (unsigned)Ww) vm |= 1u << j;
    }

    uint4 qu = *(const uint4*)(base + (size_t)pixl*768);
    const __half2 qh0 = *(__half2*)&qu.x;
    const __half2 qh1 = *(__half2*)&qu.y;
    const __half2 qh2 = *(__half2*)&qu.z;
    const __half2 qh3 = *(__half2*)&qu.w;

    // batch-load all 9 k-vectors (predicated; zero for OOB = reference's zero-pad)
    uint4 kv[9];
#pragma unroll
    for (int j = 0; j < 9; j++){
        kv[j] = make_uint4(0,0,0,0);
        if (vm & (1u << j)) kv[j] = *(const uint4*)(base + offs[j] + 256);
    }

    float sc[9];
#pragma unroll
    for (int j = 0; j < 9; j++){
        __half2 a0 = __hmul2(qh0, *(__half2*)&kv[j].x);
        a0 = __hfma2(qh1, *(__half2*)&kv[j].y, a0);
        __half2 a1 = __hmul2(qh2, *(__half2*)&kv[j].z);
        a1 = __hfma2(qh3, *(__half2*)&kv[j].w, a1);
        float s = __low2float(a0) + __high2float(a0) + __low2float(a1) + __high2float(a1);
#pragma unroll
        for (int o = 4; o > 0; o >>= 1) s += __shfl_xor_sync(0xffffffffu, s, o);
        sc[j] = s * 0.125f;
    }

    float mx = sc[0];
#pragma unroll
    for (int j = 1; j < 9; j++) mx = fmaxf(mx, sc[j]);
    float p[9], sum = 0.f;
#pragma unroll
    for (int j = 0; j < 9; j++){ p[j] = __expf(sc[j] - mx); sum += p[j]; }
    const float inv = __frcp_rn(sum);

    float a[8];
#pragma unroll
    for (int e = 0; e < 8; e++) a[e] = 0.f;
#pragma unroll
    for (int j = 0; j < 9; j++){
        if (vm & (1u << j)){
            uint4 vu = *(const uint4*)(base + offs[j] + 512);
            const float2 v0 = __half22float2(*(__half2*)&vu.x);
            const float2 v1 = __half22float2(*(__half2*)&vu.y);
            const float2 v2 = __half22float2(*(__half2*)&vu.z);
            const float2 v3 = __half22float2(*(__half2*)&vu.w);
            a[0] += p[j]*v0.x; a[1] += p[j]*v0.y;
            a[2] += p[j]*v1.x; a[3] += p[j]*v1.y;
            a[4] += p[j]*v2.x; a[5] += p[j]*v2.y;
            a[6] += p[j]*v3.x; a[7] += p[j]*v3.y;
        }
    }
    float* so = sOut + wid*256 + dil*64 + c0;
    *(float4*)(so)     = make_float4(a[0]*inv, a[1]*inv, a[2]*inv, a[3]*inv);
    *(float4*)(so + 4) = make_float4(a[4]*inv, a[5]*inv, a[6]*inv, a[7]*inv);
    __syncthreads();

    // fc mix + residual + LN(64): thread = (px4, ts, cq); 16-lane in-warp reduction.
    const int px4 = tid >> 6;
    const int ts  = (tid >> 4) & 3;
    const int cq  = tid & 15;
    const int c   = cq * 4;
    const float w0 = fcw[ts*4+0], w1_ = fcw[ts*4+1], w2_ = fcw[ts*4+2], w3 = fcw[ts*4+3];
    const float fb = fcb[ts];
    const float4 lg = *(const float4*)(lng + c);
    const float4 lb = *(const float4*)(lnb + c);

#pragma unroll
    for (int it = 0; it < 2; it++){
        const int px = px4 + it*4;
        const float* sp = sOut + px*256 + c;
        const float4 s0 = *(const float4*)(sp);
        const float4 s1 = *(const float4*)(sp + 64);
        const float4 s2 = *(const float4*)(sp + 128);
        const float4 s3 = *(const float4*)(sp + 192);
        const float4 own = (ts == 0) ? s0 : (ts == 1) ? s1 : (ts == 2) ? s2 : s3;
        float f[4];
        f[0] = w0*s0.x + w1_*s1.x + w2_*s2.x + w3*s3.x + fb + own.x;
        f[1] = w0*s0.y + w1_*s1.y + w2_*s2.y + w3*s3.y + fb + own.y;
        f[2] = w0*s0.z + w1_*s1.z + w2_*s2.z + w3*s3.z + fb + own.z;
        f[3] = w0*s0.w + w1_*s1.w + w2_*s2.w + w3*s3.w + fb + own.w;

        float sm = f[0] + f[1] + f[2] + f[3];
        float sq = f[0]*f[0] + f[1]*f[1] + f[2]*f[2] + f[3]*f[3];
#pragma unroll
        for (int o = 8; o > 0; o >>= 1){
            sm += __shfl_xor_sync(0xffffffffu, sm, o);
            sq += __shfl_xor_sync(0xffffffffu, sq, o);
        }
        const float mu  = sm * (1.f/64.f);
        const float var = sq * (1.f/64.f) - mu*mu;
        const float rs  = rsqrtf(var + EPSF);
        __half2 h01 = __floats2half2_rn((f[0]-mu)*rs*lg.x + lb.x, (f[1]-mu)*rs*lg.y + lb.y);
        __half2 h23 = __floats2half2_rn((f[2]-mu)*rs*lg.z + lb.z, (f[3]-mu)*rs*lg.w + lb.w);
        uint2 o2; o2.x = *(uint32_t*)&h01; o2.y = *(uint32_t*)&h23;
        *(uint2*)(y2 + (size_t)(blockIdx.x*8 + px)*256 + ts*64 + c) = o2;
    }
}

// ---------------- launch ----------------
extern "C" void kernel_launch(void* const* d_in, const int* in_sizes, int n_in,
                              void* d_out, int out_size)
{
    const float* x      = (const float*)d_in[0];
    const float* qkv_w  = (const float*)d_in[1];
    const float* qkv_b  = (const float*)d_in[2];
    const float* fc_w   = (const float*)d_in[3];
    const float* fc_b   = (const float*)d_in[4];
    const float* ln_g   = (const float*)d_in[5];
    const float* ln_b   = (const float*)d_in[6];
    const float* proj_w = (const float*)d_in[7];
    const float* proj_b = (const float*)d_in[8];
    const float* w1     = (const float*)d_in[9];
    const float* bn1_g  = (const float*)d_in[10];
    const float* bn1_b  = (const float*)d_in[11];
    const float* bn1_m  = (const float*)d_in[12];
    const float* bn1_v  = (const float*)d_in[13];
    const float* w2     = (const float*)d_in[14];
    const float* bn2_g  = (const float*)d_in[15];
    const float* bn2_b  = (const float*)d_in[16];
    const float* bn2_m  = (const float*)d_in[17];
    const float* bn2_v  = (const float*)d_in[18];
    float* out = (float*)d_out;

    __half *xT, *qkv, *y2, *x1h, *hb, *gw;
    cudaGetSymbolAddress((void**)&xT,  g_xT);
    cudaGetSymbolAddress((void**)&qkv, g_qkv);
    cudaGetSymbolAddress((void**)&y2,  g_y2);
    cudaGetSymbolAddress((void**)&x1h, g_x1h);
    cudaGetSymbolAddress((void**)&hb,  g_h);
    cudaGetSymbolAddress((void**)&gw,  g_w);

    cudaFuncSetAttribute(gemm_mma<0>, cudaFuncAttributeMaxDynamicSharedMemorySize, SMEM_BYTES);
    cudaFuncSetAttribute(gemm_mma<1>, cudaFuncAttributeMaxDynamicSharedMemorySize, SMEM_BYTES);
    cudaFuncSetAttribute(gemm_mma<2>, cudaFuncAttributeMaxDynamicSharedMemorySize, SMEM_BYTES);
    cudaFuncSetAttribute(gemm_mma<3>, cudaFuncAttributeMaxDynamicSharedMemorySize, SMEM_BYTES);

    // prep: transpose (1600 blocks) + weight conversion (512 blocks) in one launch
    prep_k<<<2112, 256>>>(x, xT, qkv_w, proj_w, w1, w2, gw);

    // 1) qkv = xT @ qkv_w^T + b : [51200][768] half
    gemm_mma<0><<<dim3(6, 400), 256, SMEM_BYTES>>>(
        xT, gw, qkv, nullptr, 256, 768, qkv_b, nullptr, nullptr, nullptr, nullptr, nullptr);

    // 2+3) attention + fc mix + LN (fused) -> y2 half
    attn_ln_k<<<NPIX/8, 256>>>(qkv, fc_w, fc_b, ln_g, ln_b, y2);

    // 4) x1 = y2 @ proj_w^T + proj_b + xT(half) -> x1h
    gemm_mma<1><<<dim3(2, 400), 256, SMEM_BYTES>>>(
        y2, gw + 196608, x1h, nullptr, 256, 256, proj_b, xT, nullptr, nullptr, nullptr, nullptr);

    // 5) h = silu(bn1(x1 @ w1^T)) : [51200][512] half
    gemm_mma<2><<<dim3(4, 400), 256, SMEM_BYTES>>>(
        x1h, gw + 262144, hb, nullptr, 256, 512, nullptr, nullptr, bn1_g, bn1_b, bn1_m, bn1_v);

    // 6) out = x1(half) + bn2(h @ w2^T) -> [B][C][HW] float
    gemm_mma<3><<<dim3(2, 400), 256, SMEM_BYTES>>>(
        hb, gw + 393216, nullptr, out, 512, 256, nullptr, x1h, bn2_g, bn2_b, bn2_m, bn2_v);
}

// round 17
// speedup vs baseline: 1.3442x; 1.0345x over previous
#include <cuda_runtime.h>
#include <cuda_fp16.h>
#include <cstdint>
#include <math.h>

#define B_  8
#define C_  256
#define Hh  80
#define Ww  80
#define HW  6400
#define NPIX 51200
#define MT_TOT 400               // NPIX/128 m-tiles
#define EPSF 1e-5f

// ---- old-style kernel (mlp2, K=512) ----
#define KC 64
#define STAGES 3
#define TSTRH 72
#define ST_B (128*TSTRH*2)
#define SMEM_BYTES (STAGES*2*ST_B)   // 110592

// ---- weights-stationary kernel (K=256) ----
#define PB_STR 264                   // B smem row stride (halfs)
#define PA_ST (128*40*2)             // 10240 B per A stage
#define PSMEM (128*PB_STR*2 + 4*PA_ST)   // 67584 + 40960 = 108544

// ---------------- scratch ----------------
__device__ __half g_xT [(size_t)NPIX*256];
__device__ __half g_qkv[(size_t)NPIX*768];
__device__ __half g_y2 [(size_t)NPIX*256];
__device__ __half g_x1h[(size_t)NPIX*256];
__device__ __half g_h  [(size_t)NPIX*512];
__device__ __half g_w  [524288];

// ---------------- helpers ----------------
__device__ __forceinline__ uint32_t s2u(const void* p){
    uint32_t a; asm("{ .reg .u64 t; cvta.to.shared.u64 t, %1; cvt.u32.u64 %0, t; }" : "=r"(a) : "l"(p)); return a;
}
#define CPA16(d,s) asm volatile("cp.async.cg.shared.global [%0], [%1], 16;" :: "r"(d), "l"(s))
#define CPCOMMIT() asm volatile("cp.async.commit_group;" ::: "memory")
#define CPWAIT(n)  asm volatile("cp.async.wait_group %0;" :: "n"(n) : "memory")
#define LDSM4(r0,r1,r2,r3,a) \
    asm volatile("ldmatrix.sync.aligned.m8n8.x4.shared.b16 {%0,%1,%2,%3}, [%4];" \
        : "=r"(r0), "=r"(r1), "=r"(r2), "=r"(r3) : "r"(a))

__device__ __forceinline__ void mma16(float* d, const uint32_t* a, uint32_t b0, uint32_t b1){
    asm volatile("mma.sync.aligned.m16n8k16.row.col.f32.f16.f16.f32 "
        "{%0,%1,%2,%3}, {%4,%5,%6,%7}, {%8,%9}, {%0,%1,%2,%3};"
        : "+f"(d[0]), "+f"(d[1]), "+f"(d[2]), "+f"(d[3])
        : "r"(a[0]), "r"(a[1]), "r"(a[2]), "r"(a[3]), "r"(b0), "r"(b1));
}

// ---------------- weights-stationary persistent GEMM (K=256) ----------------
// B slice (128 x 256 half) resident in smem; CTA loops m-tiles mt = by + i*gridDim.y.
// MODE 0: Ch = acc + bias[n]                       -> qkv (Cstride 768)
// MODE 1: Ch = half(acc+bias+res(half [pix][c]))   -> x1h (Cstride 256)
// MODE 2: Ch = half(silu(acc*sc+sh))               -> h   (Cstride 512)
template<int MODE>
__global__ __launch_bounds__(256, 2) void gemm_ws(
    const __half* __restrict__ A, const __half* __restrict__ Bw,
    __half* __restrict__ Ch, int Cstride,
    const float* __restrict__ bias, const __half* __restrict__ resh,
    const float* __restrict__ gg, const float* __restrict__ bb,
    const float* __restrict__ mm, const float* __restrict__ vv)
{
    extern __shared__ __half smemh[];
    const uint32_t smB = s2u(smemh);
    const uint32_t smA = smB + 128*PB_STR*2;

    const int tid  = threadIdx.x;
    const int wid  = tid >> 5;
    const int lane = tid & 31;
    const int wm   = wid & 1;
    const int wn   = wid >> 1;
    const int lr   = lane >> 2;
    const int lc   = lane & 3;
    const int n0   = blockIdx.x * 128;
    const int by   = blockIdx.y;
    const int gy   = gridDim.y;

    // load resident B (one cp.async group)
    {
        const __half* Bb = Bw + (size_t)n0 * 256;
#pragma unroll
        for (int t = 0; t < 16; t++){
            int i = tid + t*256;
            int r = i >> 5, c16 = i & 31;
            CPA16(smB + r*PB_STR*2 + c16*16, (const void*)(Bb + (size_t)r*256 + c16*8));
        }
        CPCOMMIT();
    }

    const int NT = (MT_TOT - by + gy - 1) / gy;
    const int G  = NT * 8;

    auto loadA = [&](int g){
        const int mt = by + (g >> 3) * gy;
        const int cc = g & 7;
        const __half* Ab = A + (size_t)mt*128*256 + cc*32;
        const uint32_t da = smA + (g & 3)*PA_ST;
#pragma unroll
        for (int t = 0; t < 2; t++){
            int i = tid + t*256;
            int r = i >> 2, c = i & 3;
            CPA16(da + r*40*2 + c*16, (const void*)(Ab + (size_t)r*256 + c*8));
        }
        CPCOMMIT();
    };

    loadA(0); loadA(1); loadA(2);

    const uint32_t aoff = (uint32_t)(((wm*64 + ((lane>>3)&1)*8 + (lane&7))*40 + (lane>>4)*8) * 2);
    const uint32_t boff = (uint32_t)(((wn*32 + (lane>>4)*8 + (lane&7))*PB_STR + ((lane>>3)&1)*8) * 2);
    const int lc2 = lc * 2;

    int g = 0;
    for (int ti = 0; ti < NT; ti++){
        const int mt = by + ti * gy;
        const int m0 = mt * 128;

        float d[4][4][4];
#pragma unroll
        for (int i = 0; i < 4; i++)
#pragma unroll
            for (int j = 0; j < 4; j++)
#pragma unroll
                for (int e = 0; e < 4; e++) d[i][j][e] = 0.f;

        for (int cc = 0; cc < 8; cc++, g++){
            CPWAIT(2);
            __syncthreads();
            if (g + 3 < G) loadA(g + 3);

            const uint32_t aBase = smA + (g & 3)*PA_ST + aoff;
            const uint32_t bBase = smB + boff + (uint32_t)(cc * 64);   // 2 ks-steps * 32B
#pragma unroll
            for (int kk = 0; kk < 2; kk++){
                uint32_t a[4][4], bf[2][4];
#pragma unroll
                for (int mi = 0; mi < 4; mi++)
                    LDSM4(a[mi][0], a[mi][1], a[mi][2], a[mi][3],
                          aBase + mi*(16*40*2) + kk*32);
#pragma unroll
                for (int np = 0; np < 2; np++)
                    LDSM4(bf[np][0], bf[np][1], bf[np][2], bf[np][3],
                          bBase + np*(16*PB_STR*2) + kk*32);
#pragma unroll
                for (int np = 0; np < 2; np++)
#pragma unroll
                    for (int mi = 0; mi < 4; mi++){
                        mma16(d[mi][2*np],   a[mi], bf[np][0], bf[np][1]);
                        mma16(d[mi][2*np+1], a[mi], bf[np][2], bf[np][3]);
                    }
            }
        }

        // epilogue (register-only; overlaps next tile's A prefetch)
#pragma unroll
        for (int mi = 0; mi < 4; mi++){
#pragma unroll
            for (int rr = 0; rr < 2; rr++){
                const int rl = wm*64 + mi*16 + lr + rr*8;
                const int r  = m0 + rl;
                __half* crow = Ch + (size_t)r*Cstride + n0 + wn*32;
                const __half* rrow = (MODE == 1) ? resh + (size_t)r*256 + n0 + wn*32 : (const __half*)0;
#pragma unroll
                for (int ni = 0; ni < 4; ni++){
                    const int c = ni*8 + lc2;
                    const int gc = n0 + wn*32 + c;
                    float v0 = d[mi][ni][rr*2+0];
                    float v1 = d[mi][ni][rr*2+1];
                    if (MODE == 0){
                        v0 += bias[gc]; v1 += bias[gc+1];
                        *(__half2*)(crow + c) = __floats2half2_rn(v0, v1);
                    } else if (MODE == 1){
                        const float2 rf = __half22float2(*(const __half2*)(rrow + c));
                        v0 += bias[gc]   + rf.x;
                        v1 += bias[gc+1] + rf.y;
                        *(__half2*)(crow + c) = __floats2half2_rn(v0, v1);
                    } else {
                        float i0 = gg[gc]   * rsqrtf(vv[gc]   + EPSF);
                        float i1 = gg[gc+1] * rsqrtf(vv[gc+1] + EPSF);
                        v0 = v0*i0 + (bb[gc]   - mm[gc]  *i0);
                        v1 = v1*i1 + (bb[gc+1] - mm[gc+1]*i1);
                        v0 = v0 * __frcp_rn(1.f + __expf(-v0));
                        v1 = v1 * __frcp_rn(1.f + __expf(-v1));
                        *(__half2*)(crow + c) = __floats2half2_rn(v0, v1);
                    }
                }
            }
        }
    }
}

// ---------------- old GEMM kernel (kept for mlp2, K=512, MODE 3) ----------------
template<int MODE>
__global__ __launch_bounds__(256, 2) void gemm_mma(
    const __half* __restrict__ A, const __half* __restrict__ Bw,
    __half* __restrict__ Ch, float* __restrict__ Cf, int Ktot, int Cstride,
    const float* __restrict__ bias, const __half* __restrict__ resh,
    const float* __restrict__ gg, const float* __restrict__ bb,
    const float* __restrict__ mm, const float* __restrict__ vv)
{
    extern __shared__ float smemf[];
    const uint32_t smem_b = s2u(smemf);

    const int tid  = threadIdx.x;
    const int wid  = tid >> 5;
    const int lane = tid & 31;
    const int wm   = wid & 1;
    const int wn   = wid >> 1;
    const int lr   = lane >> 2;
    const int lc   = lane & 3;
    const int m0   = blockIdx.y * 128;
    const int n0   = blockIdx.x * 128;

    const uint32_t aoff = (uint32_t)(((wm*64 + ((lane>>3)&1)*8 + (lane&7))*TSTRH + (lane>>4)*8) * 2);
    const uint32_t boff = (uint32_t)(((wn*32 + (lane>>4)*8 + (lane&7))*TSTRH + ((lane>>3)&1)*8) * 2);

    float d[4][4][4];
#pragma unroll
    for (int i = 0; i < 4; i++)
#pragma unroll
        for (int j = 0; j < 4; j++)
#pragma unroll
            for (int e = 0; e < 4; e++) d[i][j][e] = 0.f;

    const int nch = Ktot / KC;

    auto load = [&](int cc){
        const int s = cc % STAGES;
        const __half* Ab = A + (size_t)m0 * Ktot + cc*KC;
        const uint32_t da = smem_b + (2*s)*ST_B;
#pragma unroll
        for (int t = 0; t < 4; t++){
            int i = tid + t*256;
            int r = i >> 3, c = i & 7;
            CPA16(da + r*TSTRH*2 + c*16, (const void*)(Ab + (size_t)r*Ktot + c*8));
        }
        const __half* Bb = Bw + (size_t)n0 * Ktot + cc*KC;
        const uint32_t db = smem_b + (2*s+1)*ST_B;
#pragma unroll
        for (int t = 0; t < 4; t++){
            int i = tid + t*256;
            int r = i >> 3, c = i & 7;
            CPA16(db + r*TSTRH*2 + c*16, (const void*)(Bb + (size_t)r*Ktot + c*8));
        }
        CPCOMMIT();
    };

    load(0); load(1);

    for (int cc = 0; cc < nch; cc++){
        const int rem = nch - 1 - cc;
        if (rem >= 1) CPWAIT(1);
        else          CPWAIT(0);
        __syncthreads();
        if (cc + 2 < nch) load(cc + 2);

        const int s = cc % STAGES;
        const uint32_t aBase = smem_b + (2*s)*ST_B + aoff;
        const uint32_t bBase = smem_b + (2*s+1)*ST_B + boff;
#pragma unroll
        for (int kk = 0; kk < 4; kk++){
            uint32_t a[4][4], bf[2][4];
#pragma unroll
            for (int mi = 0; mi < 4; mi++)
                LDSM4(a[mi][0], a[mi][1], a[mi][2], a[mi][3],
                      aBase + mi*(16*TSTRH*2) + kk*32);
#pragma unroll
            for (int np = 0; np < 2; np++)
                LDSM4(bf[np][0], bf[np][1], bf[np][2], bf[np][3],
                      bBase + np*(16*TSTRH*2) + kk*32);
#pragma unroll
            for (int np = 0; np < 2; np++)
#pragma unroll
                for (int mi = 0; mi < 4; mi++){
                    mma16(d[mi][2*np],   a[mi], bf[np][0], bf[np][1]);
                    mma16(d[mi][2*np+1], a[mi], bf[np][2], bf[np][3]);
                }
        }
    }

    const int lc2 = lc * 2;
    // MODE 3: bn2 + residual (half x1), smem-transposed coalesced store to [b][c][hw]
    __syncthreads();
    float* stg = smemf + wid * (64*33);
#pragma unroll
    for (int ni = 0; ni < 4; ni++){
        const int gc = n0 + wn*32 + ni*8 + lc2;
        const float i0 = gg[gc]   * rsqrtf(vv[gc]   + EPSF);
        const float i1 = gg[gc+1] * rsqrtf(vv[gc+1] + EPSF);
        const float s0 = bb[gc]   - mm[gc]  *i0;
        const float s1 = bb[gc+1] - mm[gc+1]*i1;
#pragma unroll
        for (int mi = 0; mi < 4; mi++){
#pragma unroll
            for (int rr = 0; rr < 2; rr++){
                const int lrow = mi*16 + lr + rr*8;
                const int grow = m0 + wm*64 + lrow;
                const float2 rf = __half22float2(*(const __half2*)(resh + (size_t)grow*256 + gc));
                stg[lrow*33 + ni*8 + lc2]     = d[mi][ni][rr*2+0]*i0 + s0 + rf.x;
                stg[lrow*33 + ni*8 + lc2 + 1] = d[mi][ni][rr*2+1]*i1 + s1 + rf.y;
            }
        }
    }
    __syncwarp();
    const int pix0 = m0 + wm*64;
    const int bidx = pix0 / HW;
    const int pixl = pix0 - bidx*HW;
    float* ob = Cf + (size_t)bidx*C_*HW + pixl;
#pragma unroll
    for (int n = 0; n < 32; n++){
        const int gc = n0 + wn*32 + n;
        ob[(size_t)gc*HW + lane]      = stg[lane*33 + n];
        ob[(size_t)gc*HW + lane + 32] = stg[(lane+32)*33 + n];
    }
}

// ---------------- prep: transpose x -> xT half AND convert weights ----------------
__global__ __launch_bounds__(256) void prep_k(const float* __restrict__ x,
                                              __half* __restrict__ xT,
                                              const float* __restrict__ qkvw,
                                              const float* __restrict__ projw,
                                              const float* __restrict__ w1,
                                              const float* __restrict__ w2,
                                              __half* __restrict__ gw)
{
    const int blk = blockIdx.x;
    if (blk < 1600){
        const int b  = blk / 200;
        const int rm = blk - b*200;
        const int ct = rm / 25;
        const int ht = rm - ct*25;
        __shared__ float t[32][33];
        const int tid = threadIdx.x;
        const int tx = tid & 7;
        const int ty = tid >> 3;
        const int c0 = ct * 32;
        for (int sub = 0; sub < 8; sub++){
            const int hw0 = ht*256 + sub*32;
            const float4 v = *(const float4*)(x + (size_t)b*C_*HW + (size_t)(c0+ty)*HW + hw0 + tx*4);
            t[ty][tx*4+0] = v.x; t[ty][tx*4+1] = v.y; t[ty][tx*4+2] = v.z; t[ty][tx*4+3] = v.w;
            __syncthreads();
            const float f0 = t[tx*4+0][ty], f1 = t[tx*4+1][ty];
            const float f2 = t[tx*4+2][ty], f3 = t[tx*4+3][ty];
            uint2 o;
            __half2 h01 = __floats2half2_rn(f0, f1);
            __half2 h23 = __floats2half2_rn(f2, f3);
            o.x = *(uint32_t*)&h01; o.y = *(uint32_t*)&h23;
            *(uint2*)(xT + (size_t)(b*HW + hw0 + ty)*256 + c0 + tx*4) = o;
            __syncthreads();
        }
    } else {
        const int i4 = (blk - 1600) * 256 + threadIdx.x;
        const int i = i4 * 4;
        const float* src;
        if (i < 196608)      src = qkvw + i;
        else if (i < 262144) src = projw + (i - 196608);
        else if (i < 393216) src = w1 + (i - 262144);
        else                 src = w2 + (i - 393216);
        const float4 v = *(const float4*)src;
        __half2 h01 = __floats2half2_rn(v.x, v.y);
        __half2 h23 = __floats2half2_rn(v.z, v.w);
        uint2 o; o.x = *(uint32_t*)&h01; o.y = *(uint32_t*)&h23;
        *(uint2*)(gw + i) = o;
    }
}

// ---------------- fused attention + fc-mix + LayerNorm ----------------
// Zero-padded neighbors participate in softmax (reference _unfold3 semantics).
__global__ __launch_bounds__(256) void attn_ln_k(
    const __half* __restrict__ qkv,
    const float* __restrict__ fcw, const float* __restrict__ fcb,
    const float* __restrict__ lng, const float* __restrict__ lnb,
    __half* __restrict__ y2)
{
    __shared__ float sOut[2048];

    const int tid  = threadIdx.x;
    const int wid  = tid >> 5;
    const int lane = tid & 31;
    const int dil  = lane >> 3;
    const int c0   = (lane & 7) * 8;
    const int pix  = blockIdx.x * 8 + wid;
    const int b    = pix / HW;
    const int pixl = pix - b * HW;
    const int y    = pixl / Ww;
    const int x    = pixl - y * Ww;
    const int r    = 1 << dil;

    const __half* base = qkv + (size_t)b * HW * 768 + dil*64 + c0;

    int offs[9]; unsigned vm = 0;
#pragma unroll
    for (int j = 0; j < 9; j++){
        const int yy = y + (j/3 - 1) * r;
        const int xx = x + (j%3 - 1) * r;
        offs[j] = (yy*Ww + xx) * 768;
        if ((unsigned)yy < (unsigned)Hh && (unsigned)xx < (unsigned)Ww) vm |= 1u << j;
    }

    uint4 qu = *(const uint4*)(base + (size_t)pixl*768);
    const __half2 qh0 = *(__half2*)&qu.x;
    const __half2 qh1 = *(__half2*)&qu.y;
    const __half2 qh2 = *(__half2*)&qu.z;
    const __half2 qh3 = *(__half2*)&qu.w;

    uint4 kv[9];
#pragma unroll
    for (int j = 0; j < 9; j++){
        kv[j] = make_uint4(0,0,0,0);
        if (vm & (1u << j)) kv[j] = *(const uint4*)(base + offs[j] + 256);
    }

    float sc[9];
#pragma unroll
    for (int j = 0; j < 9; j++){
        __half2 a0 = __hmul2(qh0, *(__half2*)&kv[j].x);
        a0 = __hfma2(qh1, *(__half2*)&kv[j].y, a0);
        __half2 a1 = __hmul2(qh2, *(__half2*)&kv[j].z);
        a1 = __hfma2(qh3, *(__half2*)&kv[j].w, a1);
        float s = __low2float(a0) + __high2float(a0) + __low2float(a1) + __high2float(a1);
#pragma unroll
        for (int o = 4; o > 0; o >>= 1) s += __shfl_xor_sync(0xffffffffu, s, o);
        sc[j] = s * 0.125f;
    }

    float mx = sc[0];
#pragma unroll
    for (int j = 1; j < 9; j++) mx = fmaxf(mx, sc[j]);
    float p[9], sum = 0.f;
#pragma unroll
    for (int j = 0; j < 9; j++){ p[j] = __expf(sc[j] - mx); sum += p[j]; }
    const float inv = __frcp_rn(sum);

    float a[8];
#pragma unroll
    for (int e = 0; e < 8; e++) a[e] = 0.f;
#pragma unroll
    for (int j = 0; j < 9; j++){
        if (vm & (1u << j)){
            uint4 vu = *(const uint4*)(base + offs[j] + 512);
            const float2 v0 = __half22float2(*(__half2*)&vu.x);
            const float2 v1 = __half22float2(*(__half2*)&vu.y);
            const float2 v2 = __half22float2(*(__half2*)&vu.z);
            const float2 v3 = __half22float2(*(__half2*)&vu.w);
            a[0] += p[j]*v0.x; a[1] += p[j]*v0.y;
            a[2] += p[j]*v1.x; a[3] += p[j]*v1.y;
            a[4] += p[j]*v2.x; a[5] += p[j]*v2.y;
            a[6] += p[j]*v3.x; a[7] += p[j]*v3.y;
        }
    }
    float* so = sOut + wid*256 + dil*64 + c0;
    *(float4*)(so)     = make_float4(a[0]*inv, a[1]*inv, a[2]*inv, a[3]*inv);
    *(float4*)(so + 4) = make_float4(a[4]*inv, a[5]*inv, a[6]*inv, a[7]*inv);
    __syncthreads();

    const int px4 = tid >> 6;
    const int ts  = (tid >> 4) & 3;
    const int cq  = tid & 15;
    const int c   = cq * 4;
    const float w0 = fcw[ts*4+0], w1_ = fcw[ts*4+1], w2_ = fcw[ts*4+2], w3 = fcw[ts*4+3];
    const float fb = fcb[ts];
    const float4 lg = *(const float4*)(lng + c);
    const float4 lb = *(const float4*)(lnb + c);

#pragma unroll
    for (int it = 0; it < 2; it++){
        const int px = px4 + it*4;
        const float* sp = sOut + px*256 + c;
        const float4 s0 = *(const float4*)(sp);
        const float4 s1 = *(const float4*)(sp + 64);
        const float4 s2 = *(const float4*)(sp + 128);
        const float4 s3 = *(const float4*)(sp + 192);
        const float4 own = (ts == 0) ? s0 : (ts == 1) ? s1 : (ts == 2) ? s2 : s3;
        float f[4];
        f[0] = w0*s0.x + w1_*s1.x + w2_*s2.x + w3*s3.x + fb + own.x;
        f[1] = w0*s0.y + w1_*s1.y + w2_*s2.y + w3*s3.y + fb + own.y;
        f[2] = w0*s0.z + w1_*s1.z + w2_*s2.z + w3*s3.z + fb + own.z;
        f[3] = w0*s0.w + w1_*s1.w + w2_*s2.w + w3*s3.w + fb + own.w;

        float sm = f[0] + f[1] + f[2] + f[3];
        float sq = f[0]*f[0] + f[1]*f[1] + f[2]*f[2] + f[3]*f[3];
#pragma unroll
        for (int o = 8; o > 0; o >>= 1){
            sm += __shfl_xor_sync(0xffffffffu, sm, o);
            sq += __shfl_xor_sync(0xffffffffu, sq, o);
        }
        const float mu  = sm * (1.f/64.f);
        const float var = sq * (1.f/64.f) - mu*mu;
        const float rs  = rsqrtf(var + EPSF);
        __half2 h01 = __floats2half2_rn((f[0]-mu)*rs*lg.x + lb.x, (f[1]-mu)*rs*lg.y + lb.y);
        __half2 h23 = __floats2half2_rn((f[2]-mu)*rs*lg.z + lb.z, (f[3]-mu)*rs*lg.w + lb.w);
        uint2 o2; o2.x = *(uint32_t*)&h01; o2.y = *(uint32_t*)&h23;
        *(uint2*)(y2 + (size_t)(blockIdx.x*8 + px)*256 + ts*64 + c) = o2;
    }
}

// ---------------- launch ----------------
extern "C" void kernel_launch(void* const* d_in, const int* in_sizes, int n_in,
                              void* d_out, int out_size)
{
    const float* x      = (const float*)d_in[0];
    const float* qkv_w  = (const float*)d_in[1];
    const float* qkv_b  = (const float*)d_in[2];
    const float* fc_w   = (const float*)d_in[3];
    const float* fc_b   = (const float*)d_in[4];
    const float* ln_g   = (const float*)d_in[5];
    const float* ln_b   = (const float*)d_in[6];
    const float* proj_w = (const float*)d_in[7];
    const float* proj_b = (const float*)d_in[8];
    const float* w1     = (const float*)d_in[9];
    const float* bn1_g  = (const float*)d_in[10];
    const float* bn1_b  = (const float*)d_in[11];
    const float* bn1_m  = (const float*)d_in[12];
    const float* bn1_v  = (const float*)d_in[13];
    const float* w2     = (const float*)d_in[14];
    const float* bn2_g  = (const float*)d_in[15];
    const float* bn2_b  = (const float*)d_in[16];
    const float* bn2_m  = (const float*)d_in[17];
    const float* bn2_v  = (const float*)d_in[18];
    float* out = (float*)d_out;

    __half *xT, *qkv, *y2, *x1h, *hb, *gw;
    cudaGetSymbolAddress((void**)&xT,  g_xT);
    cudaGetSymbolAddress((void**)&qkv, g_qkv);
    cudaGetSymbolAddress((void**)&y2,  g_y2);
    cudaGetSymbolAddress((void**)&x1h, g_x1h);
    cudaGetSymbolAddress((void**)&hb,  g_h);
    cudaGetSymbolAddress((void**)&gw,  g_w);

    cudaFuncSetAttribute(gemm_ws<0>, cudaFuncAttributeMaxDynamicSharedMemorySize, PSMEM);
    cudaFuncSetAttribute(gemm_ws<1>, cudaFuncAttributeMaxDynamicSharedMemorySize, PSMEM);
    cudaFuncSetAttribute(gemm_ws<2>, cudaFuncAttributeMaxDynamicSharedMemorySize, PSMEM);
    cudaFuncSetAttribute(gemm_mma<3>, cudaFuncAttributeMaxDynamicSharedMemorySize, SMEM_BYTES);

    // prep: transpose (1600 blocks) + weight conversion (512 blocks)
    prep_k<<<2112, 256>>>(x, xT, qkv_w, proj_w, w1, w2, gw);

    // 1) qkv = xT @ qkv_w^T + b : [51200][768]  (300 persistent CTAs, 8 m-tiles each)
    gemm_ws<0><<<dim3(6, 50), 256, PSMEM>>>(
        xT, gw, qkv, 768, qkv_b, nullptr, nullptr, nullptr, nullptr, nullptr);

    // 2+3) attention + fc mix + LN (fused) -> y2 half
    attn_ln_k<<<NPIX/8, 256>>>(qkv, fc_w, fc_b, ln_g, ln_b, y2);

    // 4) x1 = y2 @ proj_w^T + proj_b + xT(half) -> x1h  (296 persistent CTAs)
    gemm_ws<1><<<dim3(2, 148), 256, PSMEM>>>(
        y2, gw + 196608, x1h, 256, proj_b, xT, nullptr, nullptr, nullptr, nullptr);

    // 5) h = silu(bn1(x1 @ w1^T)) : [51200][512]  (296 persistent CTAs)
    gemm_ws<2><<<dim3(4, 74), 256, PSMEM>>>(
        x1h, gw + 262144, hb, 512, nullptr, nullptr, bn1_g, bn1_b, bn1_m, bn1_v);

    // 6) out = x1(half) + bn2(h @ w2^T) -> [B][C][HW] float (K=512, old kernel)
    gemm_mma<3><<<dim3(2, 400), 256, SMEM_BYTES>>>(
        hb, gw + 393216, nullptr, out, 512, 256, nullptr, x1h, bn2_g, bn2_b, bn2_m, bn2_v);
}